// round 3
// baseline (speedup 1.0000x reference)
#include <cuda_runtime.h>
#include <cuda_bf16.h>
#include <cstdint>

#define B_   64
#define T_   512
#define IN_  256
#define OUT_ 256
#define H_   512
#define MROWS (B_*T_)          // 32768
#define OUT_OFF (B_*T_*OUT_)   // 8388608 : offset of "hidden" in d_out

// ---------------- device scratch (no cudaMalloc allowed) ----------------
__device__ __align__(16) float2 g_u[MROWS*H_];                 // 128 MB
__device__ __align__(16) __nv_bfloat16 g_outsH[MROWS*2*H_];    // 64 MB
__device__ __align__(16) __nv_bfloat16 g_outsL[MROWS*2*H_];    // 64 MB
__device__ __align__(16) __nv_bfloat16 g_xH[MROWS*IN_];
__device__ __align__(16) __nv_bfloat16 g_xL[MROWS*IN_];
__device__ __align__(16) __nv_bfloat16 g_w1H[2*H_*IN_];
__device__ __align__(16) __nv_bfloat16 g_w1L[2*H_*IN_];
__device__ __align__(16) __nv_bfloat16 g_w2H[OUT_*2*H_];
__device__ __align__(16) __nv_bfloat16 g_w2L[OUT_*2*H_];

__device__ __forceinline__ float2 cmul(float2 a, float2 b) {
    return make_float2(a.x*b.x - a.y*b.y, a.x*b.y + a.y*b.x);
}

// =========================================================================
// split kernels: fp32 -> (hi, lo) bf16
// =========================================================================
template<int WHICH>
__global__ void split_kernel(const float* __restrict__ src, int n4)
{
    __nv_bfloat16 *hi, *lo;
    if (WHICH == 0) { hi = g_xH;  lo = g_xL;  }
    if (WHICH == 1) { hi = g_w1H; lo = g_w1L; }
    if (WHICH == 2) { hi = g_w2H; lo = g_w2L; }
    int i = blockIdx.x * blockDim.x + threadIdx.x;
    if (i >= n4) return;
    float4 v = ((const float4*)src)[i];
    const float* pv = (const float*)&v;
    #pragma unroll
    for (int j = 0; j < 4; j++) {
        __nv_bfloat16 h = __float2bfloat16(pv[j]);
        hi[4*i + j] = h;
        lo[4*i + j] = __float2bfloat16(pv[j] - __bfloat162float(h));
    }
}

// =========================================================================
// radix-4 Stockham stage; 128 threads, one butterfly each
// =========================================================================
template<int M, int INV>
__device__ __forceinline__ void r4(const float2* __restrict__ src,
                                   float2* __restrict__ dst,
                                   float2 w1, float2 w2, int tid)
{
    const float w1y = INV ? -w1.y : w1.y;
    const float w2y = INV ? -w2.y : w2.y;
    int k = tid & (M - 1);
    float2 x0 = src[tid], x1 = src[tid+128], x2 = src[tid+256], x3 = src[tid+384];
    float2 a   = make_float2(x0.x + x2.x, x0.y + x2.y);
    float2 s02 = make_float2(x0.x - x2.x, x0.y - x2.y);
    float2 c   = make_float2(x1.x + x3.x, x1.y + x3.y);
    float2 s13 = make_float2(x1.x - x3.x, x1.y - x3.y);
    float2 b = make_float2(w1.x*s02.x - w1y*s02.y, w1.x*s02.y + w1y*s02.x);
    float2 q = INV ? make_float2(-s13.y, s13.x) : make_float2(s13.y, -s13.x);
    float2 d = make_float2(w1.x*q.x - w1y*q.y, w1.x*q.y + w1y*q.x);
    int o = 4*tid - 3*k;
    dst[o]     = make_float2(a.x + c.x, a.y + c.y);
    dst[o + M] = make_float2(b.x + d.x, b.y + d.y);
    float2 ac = make_float2(a.x - c.x, a.y - c.y);
    float2 bd = make_float2(b.x - d.x, b.y - d.y);
    dst[o + 2*M] = make_float2(w2.x*ac.x - w2y*ac.y, w2.x*ac.y + w2y*ac.x);
    dst[o + 3*M] = make_float2(w2.x*bd.x - w2y*bd.y, w2.x*bd.y + w2y*bd.x);
}

template<int INV>
__device__ __forceinline__ void r4_reg(float2 x0, float2 x1, float2 x2, float2 x3,
                                       float2* __restrict__ dst,
                                       float2 w1, float2 w2, int tid)
{
    const float w1y = INV ? -w1.y : w1.y;
    const float w2y = INV ? -w2.y : w2.y;
    float2 a   = make_float2(x0.x + x2.x, x0.y + x2.y);
    float2 s02 = make_float2(x0.x - x2.x, x0.y - x2.y);
    float2 c   = make_float2(x1.x + x3.x, x1.y + x3.y);
    float2 s13 = make_float2(x1.x - x3.x, x1.y - x3.y);
    float2 b = make_float2(w1.x*s02.x - w1y*s02.y, w1.x*s02.y + w1y*s02.x);
    float2 q = INV ? make_float2(-s13.y, s13.x) : make_float2(s13.y, -s13.x);
    float2 d = make_float2(w1.x*q.x - w1y*q.y, w1.x*q.y + w1y*q.x);
    int o = 4*tid;
    dst[o]   = make_float2(a.x + c.x, a.y + c.y);
    dst[o+1] = make_float2(b.x + d.x, b.y + d.y);
    float2 ac = make_float2(a.x - c.x, a.y - c.y);
    float2 bd = make_float2(b.x - d.x, b.y - d.y);
    dst[o+2] = make_float2(w2.x*ac.x - w2y*ac.y, w2.x*ac.y + w2y*ac.x);
    dst[o+3] = make_float2(w2.x*bd.x - w2y*bd.y, w2.x*bd.y + w2y*bd.x);
}

// =========================================================================
// Scan kernel: TWO batch rows per CTA, interleaved stage-by-stage so each
// barrier section carries two independent dependency chains (latency hiding
// with only 4 warps). 10 syncs per step serve both batches.
// =========================================================================
__global__ __launch_bounds__(128)
void scan_kernel(const float* __restrict__ h0,
                 const float* __restrict__ b_h,
                 const float* __restrict__ d1,
                 const float* __restrict__ d2,
                 const float* __restrict__ d3,
                 const float* __restrict__ r1re, const float* __restrict__ r1im,
                 const float* __restrict__ r2re, const float* __restrict__ r2im,
                 const int*   __restrict__ perm,
                 float* __restrict__ dout)
{
    __shared__ float2 SA[2][512], SB[2][512];
    __shared__ float2 V1s[512];
    __shared__ float2 RED[2][4];
    __shared__ float  FAC[2];

    const int tid = threadIdx.x;
    const int lane = tid & 31, wid = tid >> 5;
    const int b0 = blockIdx.x * 2;

    // ---- per-thread constants at idx_r = tid + 128r (shared across batches)
    float2 h[2][4], e1r[4], e2r[4], e3r[4], v1r[4], v2r[4];
    float bhr[4]; int pr[4];
    #pragma unroll
    for (int r = 0; r < 4; r++) {
        int idx = tid + 128*r;
        float sn, cs;
        sincosf(d1[idx], &sn, &cs); e1r[r] = make_float2(cs, sn);
        sincosf(d2[idx], &sn, &cs); e2r[r] = make_float2(cs, sn);
        sincosf(d3[idx], &sn, &cs); e3r[r] = make_float2(cs, sn);
        v1r[r] = make_float2(r1re[idx], r1im[idx]);
        v2r[r] = make_float2(r2re[idx], r2im[idx]);
        V1s[idx] = v1r[r];
        bhr[r] = b_h[idx];
        pr[r]  = perm[idx];
        h[0][r] = make_float2(h0[b0*1024 + idx],       h0[b0*1024 + 512 + idx]);
        h[1][r] = make_float2(h0[(b0+1)*1024 + idx],   h0[(b0+1)*1024 + 512 + idx]);
    }

    // ---- per-thread twiddles, stages m = 1,4,16,64 ----
    float2 W1[4], W2[4];
    #pragma unroll
    for (int s = 0; s < 4; s++) {
        int m = 1 << (2*s);
        int base = tid & ~(m - 1);
        float sn, cs;
        float a1 = -6.283185307179586f * (float)base / 512.0f;
        sincosf(a1, &sn, &cs); W1[s] = make_float2(cs, sn);
        float a2 = -6.283185307179586f * (float)(2*base) / 512.0f;
        sincosf(a2, &sn, &cs); W2[s] = make_float2(cs, sn);
    }

    // ---- fac1/fac2 = 2/||v||^2 (identical for both batches) ----
    {
        float n1 = 0.f, n2 = 0.f;
        #pragma unroll
        for (int r = 0; r < 4; r++) {
            n1 += v1r[r].x*v1r[r].x + v1r[r].y*v1r[r].y;
            n2 += v2r[r].x*v2r[r].x + v2r[r].y*v2r[r].y;
        }
        #pragma unroll
        for (int off = 16; off; off >>= 1) {
            n1 += __shfl_xor_sync(0xffffffffu, n1, off);
            n2 += __shfl_xor_sync(0xffffffffu, n2, off);
        }
        if (lane == 0) RED[0][wid] = make_float2(n1, n2);
        __syncthreads();
        if (tid == 0) {
            float a  = (RED[0][0].x + RED[0][1].x) + (RED[0][2].x + RED[0][3].x);
            float bb = (RED[0][0].y + RED[0][1].y) + (RED[0][2].y + RED[0][3].y);
            FAC[0] = 2.f / a; FAC[1] = 2.f / bb;
        }
        __syncthreads();
    }
    const float fac1 = FAC[0], fac2 = FAC[1];
    const int brow[2] = { b0 * T_, (b0+1) * T_ };
    const float inv512 = 1.0f / 512.0f;

    for (int t = 0; t < T_; t++) {
        // prefetch u_t for both batches
        float2 u0[2][4];
        #pragma unroll
        for (int s = 0; s < 2; s++) {
            const float2* up = g_u + (size_t)(brow[s] + t) * H_;
            #pragma unroll
            for (int r = 0; r < 4; r++) u0[s][r] = up[tid + 128*r];
        }

        // FFT stage 1 (m=1) fused h*e1, regs -> SA[s]
        #pragma unroll
        for (int s = 0; s < 2; s++)
            r4_reg<0>(cmul(h[s][0], e1r[0]), cmul(h[s][1], e1r[1]),
                      cmul(h[s][2], e1r[2]), cmul(h[s][3], e1r[3]),
                      SA[s], W1[0], W2[0], tid);
        __syncthreads();                                            // 1
        r4<4,  0>(SA[0], SB[0], W1[1], W2[1], tid);
        r4<4,  0>(SA[1], SB[1], W1[1], W2[1], tid);  __syncthreads(); // 2
        r4<16, 0>(SB[0], SA[0], W1[2], W2[2], tid);
        r4<16, 0>(SB[1], SA[1], W1[2], W2[2], tid);  __syncthreads(); // 3
        r4<64, 0>(SA[0], SB[0], W1[3], W2[3], tid);
        r4<64, 0>(SA[1], SB[1], W1[3], W2[3], tid);  __syncthreads(); // 4

        // stage 5: radix-2 m=256, SB -> z -> SA ; dot1 partials
        #pragma unroll
        for (int s = 0; s < 2; s++) {
            float2 a0 = SB[s][tid],     a1 = SB[s][tid+128];
            float2 a2 = SB[s][tid+256], a3 = SB[s][tid+384];
            float2 zt[4];
            zt[0] = make_float2(a0.x + a2.x, a0.y + a2.y);
            zt[2] = make_float2(a0.x - a2.x, a0.y - a2.y);
            zt[1] = make_float2(a1.x + a3.x, a1.y + a3.y);
            zt[3] = make_float2(a1.x - a3.x, a1.y - a3.y);
            SA[s][tid] = zt[0]; SA[s][tid+128] = zt[1];
            SA[s][tid+256] = zt[2]; SA[s][tid+384] = zt[3];
            float dx = 0.f, dy = 0.f;
            #pragma unroll
            for (int r = 0; r < 4; r++) {
                dx += zt[r].x*v1r[r].x + zt[r].y*v1r[r].y;
                dy += zt[r].y*v1r[r].x - zt[r].x*v1r[r].y;
            }
            #pragma unroll
            for (int off = 16; off; off >>= 1) {
                dx += __shfl_xor_sync(0xffffffffu, dx, off);
                dy += __shfl_xor_sync(0xffffffffu, dy, off);
            }
            if (lane == 0) RED[s][wid] = make_float2(dx, dy);
        }
        __syncthreads();                                            // 5
        float2 dot1[2];
        #pragma unroll
        for (int s = 0; s < 2; s++) {
            dot1[s].x = ((RED[s][0].x + RED[s][1].x) + (RED[s][2].x + RED[s][3].x)) * fac1;
            dot1[s].y = ((RED[s][0].y + RED[s][1].y) + (RED[s][2].y + RED[s][3].y)) * fac1;
        }

        // IFFT stage 1: fused reflect1 + permute + e2, SA -> SB
        #pragma unroll
        for (int s = 0; s < 2; s++) {
            float2 x[4];
            #pragma unroll
            for (int i = 0; i < 4; i++) {
                int p = pr[i];
                float2 zz = SA[s][p], vv = V1s[p];
                zz.x -= dot1[s].x*vv.x - dot1[s].y*vv.y;
                zz.y -= dot1[s].x*vv.y + dot1[s].y*vv.x;
                x[i] = cmul(zz, e2r[i]);
            }
            r4_reg<1>(x[0], x[1], x[2], x[3], SB[s], W1[0], W2[0], tid);
        }
        __syncthreads();                                            // 6
        r4<4,  1>(SB[0], SA[0], W1[1], W2[1], tid);
        r4<4,  1>(SB[1], SA[1], W1[1], W2[1], tid);  __syncthreads(); // 7
        r4<16, 1>(SA[0], SB[0], W1[2], W2[2], tid);
        r4<16, 1>(SA[1], SB[1], W1[2], W2[2], tid);  __syncthreads(); // 8
        r4<64, 1>(SB[0], SA[0], W1[3], W2[3], tid);
        r4<64, 1>(SB[1], SA[1], W1[3], W2[3], tid);  __syncthreads(); // 9

        // IFFT stage 5: SA -> z ; dot2 partials
        float2 z[2][4];
        #pragma unroll
        for (int s = 0; s < 2; s++) {
            float2 a0 = SA[s][tid],     a1 = SA[s][tid+128];
            float2 a2 = SA[s][tid+256], a3 = SA[s][tid+384];
            z[s][0] = make_float2(a0.x + a2.x, a0.y + a2.y);
            z[s][2] = make_float2(a0.x - a2.x, a0.y - a2.y);
            z[s][1] = make_float2(a1.x + a3.x, a1.y + a3.y);
            z[s][3] = make_float2(a1.x - a3.x, a1.y - a3.y);
            float dx = 0.f, dy = 0.f;
            #pragma unroll
            for (int r = 0; r < 4; r++) {
                dx += z[s][r].x*v2r[r].x + z[s][r].y*v2r[r].y;
                dy += z[s][r].y*v2r[r].x - z[s][r].x*v2r[r].y;
            }
            #pragma unroll
            for (int off = 16; off; off >>= 1) {
                dx += __shfl_xor_sync(0xffffffffu, dx, off);
                dy += __shfl_xor_sync(0xffffffffu, dy, off);
            }
            if (lane == 0) RED[s][wid] = make_float2(dx, dy);
        }
        __syncthreads();                                            // 10

        // epilogue per batch (registers only)
        #pragma unroll
        for (int s = 0; s < 2; s++) {
            float2 dot2;
            dot2.x = ((RED[s][0].x + RED[s][1].x) + (RED[s][2].x + RED[s][3].x)) * fac2;
            dot2.y = ((RED[s][0].y + RED[s][1].y) + (RED[s][2].y + RED[s][3].y)) * fac2;
            const int orow = (brow[s] + t) * (2*H_);
            #pragma unroll
            for (int r = 0; r < 4; r++) {
                float2 zz = z[s][r], vv = v2r[r];
                zz.x -= dot2.x*vv.x - dot2.y*vv.y;
                zz.y -= dot2.x*vv.y + dot2.y*vv.x;
                float2 e = e3r[r];
                float2 sv = make_float2((zz.x*e.x - zz.y*e.y) * inv512,
                                        (zz.x*e.y + zz.y*e.x) * inv512);
                float2 pre = make_float2(u0[s][r].x + sv.x, u0[s][r].y + sv.y);
                float norm = sqrtf(pre.x*pre.x + pre.y*pre.y);
                float sc = fmaxf(norm + bhr[r], 0.f) / (norm + 1e-6f);
                float2 nw = make_float2(pre.x*sc, pre.y*sc);
                h[s][r] = nw;
                int idx = tid + 128*r;
                __nv_bfloat16 hx = __float2bfloat16(nw.x);
                __nv_bfloat16 hy = __float2bfloat16(nw.y);
                g_outsH[orow + idx]       = hx;
                g_outsL[orow + idx]       = __float2bfloat16(nw.x - __bfloat162float(hx));
                g_outsH[orow + 512 + idx] = hy;
                g_outsL[orow + 512 + idx] = __float2bfloat16(nw.y - __bfloat162float(hy));
            }
        }
        // next step's first SA write is protected by sync 10
    }

    #pragma unroll
    for (int s = 0; s < 2; s++)
        #pragma unroll
        for (int r = 0; r < 4; r++) {
            int idx = tid + 128*r;
            dout[OUT_OFF + (b0+s)*1024 + idx]       = h[s][r].x;
            dout[OUT_OFF + (b0+s)*1024 + 512 + idx] = h[s][r].y;
        }
}

// =========================================================================
// bf16x3 GEMM: pre-split operands, cp.async double buffer, ldmatrix frags
// =========================================================================
#define MMA16816(d, a, b)                                                     \
    asm volatile("mma.sync.aligned.m16n8k16.row.col.f32.bf16.bf16.f32 "       \
                 "{%0,%1,%2,%3}, {%4,%5,%6,%7}, {%8,%9}, {%0,%1,%2,%3};\n"    \
                 : "+f"(d[0]), "+f"(d[1]), "+f"(d[2]), "+f"(d[3])             \
                 : "r"(a[0]), "r"(a[1]), "r"(a[2]), "r"(a[3]),                \
                   "r"(b[0]), "r"(b[1]))

#define LDMX4(r0, r1, r2, r3, addr)                                           \
    asm volatile("ldmatrix.sync.aligned.m8n8.x4.shared.b16 {%0,%1,%2,%3}, [%4];" \
                 : "=r"(r0), "=r"(r1), "=r"(r2), "=r"(r3) : "r"(addr))

__device__ __forceinline__ void cp16(void* dst, const void* src) {
    uint32_t d = (uint32_t)__cvta_generic_to_shared(dst);
    asm volatile("cp.async.cg.shared.global [%0], [%1], 16;\n" :: "r"(d), "l"(src));
}

// smem layout (dynamic): As[buf][hl][128][40], Bs[buf][hl][64][40]
#define AS(p, buf, hl, r, c) (p)[((((buf)*2 + (hl))*128 + (r))*40) + (c)]
#define BS(p, buf, hl, r, c) (p)[((((buf)*2 + (hl))*64  + (r))*40) + (c)]
#define GEMM_SMEM ((2*2*128*40 + 2*2*64*40) * 2)   // 61440 bytes

template<int MODE>
__global__ __launch_bounds__(256)
void gemm_bf16s(const float* __restrict__ bias,
                float* __restrict__ C, int M, int N, int K)
{
    extern __shared__ __nv_bfloat16 smem[];
    __nv_bfloat16* Asm = smem;
    __nv_bfloat16* Bsm = smem + 2*2*128*40;

    const __nv_bfloat16* AH = (MODE == 0) ? g_xH : g_outsH;
    const __nv_bfloat16* AL = (MODE == 0) ? g_xL : g_outsL;
    const __nv_bfloat16* WH = (MODE == 0) ? g_w1H : g_w2H;
    const __nv_bfloat16* WL = (MODE == 0) ? g_w1L : g_w2L;

    const int tid = threadIdx.x;
    const int wid = tid >> 5, lane = tid & 31;
    const int wm = wid >> 1, wn = wid & 1;
    const int groupID = lane >> 2, tig = lane & 3;
    const int bm0 = blockIdx.y * 128;
    const int bn0 = blockIdx.x * 64;
    const int KT = K / 32;

    const int ar0 = tid >> 2,         aq0 = (tid & 3) * 8;
    const int ar1 = (tid + 256) >> 2, aq1 = aq0;
    const int br  = tid >> 2,         bq  = (tid & 3) * 8;

    // ldmatrix lane-address components
    const int a_row = (lane & 15);            // + wm*32 + mi*16
    const int a_col = (lane >> 4) * 8;        // + kb
    const int b_row = ((lane >> 4) << 3) + (lane & 7);   // + wn*32 + nip*16
    const int b_col = ((lane >> 3) & 1) * 8;  // + kb

    float acc[2][4][4];
    #pragma unroll
    for (int mi = 0; mi < 2; mi++)
        #pragma unroll
        for (int ni = 0; ni < 4; ni++)
            #pragma unroll
            for (int j = 0; j < 4; j++) acc[mi][ni][j] = 0.f;

    auto load_tile = [&](int kt, int buf) {
        int k0 = kt * 32;
        cp16(&AS(Asm, buf, 0, ar0, aq0), AH + (size_t)(bm0 + ar0)*K + k0 + aq0);
        cp16(&AS(Asm, buf, 0, ar1, aq1), AH + (size_t)(bm0 + ar1)*K + k0 + aq1);
        cp16(&AS(Asm, buf, 1, ar0, aq0), AL + (size_t)(bm0 + ar0)*K + k0 + aq0);
        cp16(&AS(Asm, buf, 1, ar1, aq1), AL + (size_t)(bm0 + ar1)*K + k0 + aq1);
        cp16(&BS(Bsm, buf, 0, br, bq),   WH + (size_t)(bn0 + br)*K + k0 + bq);
        cp16(&BS(Bsm, buf, 1, br, bq),   WL + (size_t)(bn0 + br)*K + k0 + bq);
    };

    load_tile(0, 0);
    asm volatile("cp.async.commit_group;\n");

    for (int kt = 0; kt < KT; kt++) {
        const int buf = kt & 1;
        if (kt + 1 < KT) {
            load_tile(kt + 1, (kt + 1) & 1);
            asm volatile("cp.async.commit_group;\n");
            asm volatile("cp.async.wait_group 1;\n");
        } else {
            asm volatile("cp.async.wait_group 0;\n");
        }
        __syncthreads();

        #pragma unroll
        for (int kk = 0; kk < 2; kk++) {
            const int kb = kk * 16;
            uint32_t aH[2][4], aL[2][4], bH[4][2], bL[4][2];
            #pragma unroll
            for (int mi = 0; mi < 2; mi++) {
                uint32_t adrH = (uint32_t)__cvta_generic_to_shared(
                    &AS(Asm, buf, 0, wm*32 + mi*16 + a_row, kb + a_col));
                uint32_t adrL = (uint32_t)__cvta_generic_to_shared(
                    &AS(Asm, buf, 1, wm*32 + mi*16 + a_row, kb + a_col));
                LDMX4(aH[mi][0], aH[mi][1], aH[mi][2], aH[mi][3], adrH);
                LDMX4(aL[mi][0], aL[mi][1], aL[mi][2], aL[mi][3], adrL);
            }
            #pragma unroll
            for (int nip = 0; nip < 2; nip++) {
                uint32_t adrH = (uint32_t)__cvta_generic_to_shared(
                    &BS(Bsm, buf, 0, wn*32 + nip*16 + b_row, kb + b_col));
                uint32_t adrL = (uint32_t)__cvta_generic_to_shared(
                    &BS(Bsm, buf, 1, wn*32 + nip*16 + b_row, kb + b_col));
                LDMX4(bH[2*nip][0], bH[2*nip][1], bH[2*nip+1][0], bH[2*nip+1][1], adrH);
                LDMX4(bL[2*nip][0], bL[2*nip][1], bL[2*nip+1][0], bL[2*nip+1][1], adrL);
            }
            #pragma unroll
            for (int mi = 0; mi < 2; mi++)
                #pragma unroll
                for (int ni = 0; ni < 4; ni++) {
                    MMA16816(acc[mi][ni], aH[mi], bH[ni]);
                    MMA16816(acc[mi][ni], aH[mi], bL[ni]);
                    MMA16816(acc[mi][ni], aL[mi], bH[ni]);
                }
        }
        __syncthreads();
    }

    // ---- epilogue ----
    #pragma unroll
    for (int mi = 0; mi < 2; mi++) {
        #pragma unroll
        for (int ni = 0; ni < 4; ni++) {
            int r0 = bm0 + wm*32 + mi*16 + groupID;
            int c0 = bn0 + wn*32 + ni*8 + 2*tig;
            float v00 = acc[mi][ni][0], v01 = acc[mi][ni][1];
            float v10 = acc[mi][ni][2], v11 = acc[mi][ni][3];
            if (MODE == 0) {
                #pragma unroll
                for (int q = 0; q < 4; q++) {
                    int rr = (q < 2) ? r0 : (r0 + 8);
                    int cc = (q & 1) ? (c0 + 1) : c0;
                    float vv = (q==0)?v00:(q==1)?v01:(q==2)?v10:v11;
                    if (cc < 512) g_u[(size_t)rr*512 + cc].x = vv;
                    else          g_u[(size_t)rr*512 + cc - 512].y = vv;
                }
            } else {
                float b0 = bias[c0], b1 = bias[c0 + 1];
                C[(size_t)r0*N + c0]         = v00 + b0;
                C[(size_t)r0*N + c0 + 1]     = v01 + b1;
                C[(size_t)(r0+8)*N + c0]     = v10 + b0;
                C[(size_t)(r0+8)*N + c0 + 1] = v11 + b1;
            }
        }
    }
}

// =========================================================================
extern "C" void kernel_launch(void* const* d_in, const int* in_sizes, int n_in,
                              void* d_out, int out_size)
{
    const float* x    = (const float*)d_in[0];
    const float* h0   = (const float*)d_in[1];
    const float* itoh = (const float*)d_in[2];
    const float* fcw  = (const float*)d_in[3];
    const float* fcb  = (const float*)d_in[4];
    const float* bh   = (const float*)d_in[5];
    const float* d1   = (const float*)d_in[6];
    const float* d2   = (const float*)d_in[7];
    const float* d3   = (const float*)d_in[8];
    const float* r1re = (const float*)d_in[9];
    const float* r1im = (const float*)d_in[10];
    const float* r2re = (const float*)d_in[11];
    const float* r2im = (const float*)d_in[12];
    const int*   perm = (const int*)d_in[13];
    float* out = (float*)d_out;

    cudaFuncSetAttribute(gemm_bf16s<0>, cudaFuncAttributeMaxDynamicSharedMemorySize, GEMM_SMEM);
    cudaFuncSetAttribute(gemm_bf16s<1>, cudaFuncAttributeMaxDynamicSharedMemorySize, GEMM_SMEM);

    {
        int n4 = (MROWS*IN_) / 4;
        split_kernel<0><<<(n4 + 255)/256, 256>>>(x, n4);
        n4 = (2*H_*IN_) / 4;
        split_kernel<1><<<(n4 + 255)/256, 256>>>(itoh, n4);
        n4 = (OUT_*2*H_) / 4;
        split_kernel<2><<<(n4 + 255)/256, 256>>>(fcw, n4);
    }

    // GEMM1: u = x @ itoh^T  (M=32768, N=1024, K=256) -> g_u
    gemm_bf16s<0><<<dim3(1024/64, MROWS/128), 256, GEMM_SMEM>>>(nullptr, nullptr,
                                                                MROWS, 1024, 256);
    // scan: 2 batches per CTA
    scan_kernel<<<B_/2, 128>>>(h0, bh, d1, d2, d3, r1re, r1im, r2re, r2im, perm, out);
    // GEMM2: outputs = outs @ fc_w^T + fc_b  (M=32768, N=256, K=1024)
    gemm_bf16s<1><<<dim3(256/64, MROWS/128), 256, GEMM_SMEM>>>(fcb, out,
                                                               MROWS, 256, 1024);
}

// round 4
// speedup vs baseline: 1.1668x; 1.1668x over previous
#include <cuda_runtime.h>
#include <cuda_bf16.h>
#include <cstdint>

#define B_   64
#define T_   512
#define IN_  256
#define OUT_ 256
#define H_   512
#define MROWS (B_*T_)          // 32768
#define OUT_OFF (B_*T_*OUT_)   // 8388608 : offset of "hidden" in d_out

// ---------------- device scratch (no cudaMalloc allowed) ----------------
__device__ __align__(16) float2 g_u[MROWS*H_];                 // 128 MB
__device__ __align__(16) __nv_bfloat16 g_outsH[MROWS*2*H_];    // 64 MB
__device__ __align__(16) __nv_bfloat16 g_outsL[MROWS*2*H_];    // 64 MB
__device__ __align__(16) __nv_bfloat16 g_xH[MROWS*IN_];
__device__ __align__(16) __nv_bfloat16 g_xL[MROWS*IN_];
__device__ __align__(16) __nv_bfloat16 g_w1H[2*H_*IN_];
__device__ __align__(16) __nv_bfloat16 g_w1L[2*H_*IN_];
__device__ __align__(16) __nv_bfloat16 g_w2H[OUT_*2*H_];
__device__ __align__(16) __nv_bfloat16 g_w2L[OUT_*2*H_];

__device__ __forceinline__ float2 cmul(float2 a, float2 b) {
    return make_float2(a.x*b.x - a.y*b.y, a.x*b.y + a.y*b.x);
}

// =========================================================================
// split kernels: fp32 -> (hi, lo) bf16
// =========================================================================
template<int WHICH>
__global__ void split_kernel(const float* __restrict__ src, int n4)
{
    __nv_bfloat16 *hi, *lo;
    if (WHICH == 0) { hi = g_xH;  lo = g_xL;  }
    if (WHICH == 1) { hi = g_w1H; lo = g_w1L; }
    if (WHICH == 2) { hi = g_w2H; lo = g_w2L; }
    int i = blockIdx.x * blockDim.x + threadIdx.x;
    if (i >= n4) return;
    float4 v = ((const float4*)src)[i];
    const float* pv = (const float*)&v;
    #pragma unroll
    for (int j = 0; j < 4; j++) {
        __nv_bfloat16 h = __float2bfloat16(pv[j]);
        hi[4*i + j] = h;
        lo[4*i + j] = __float2bfloat16(pv[j] - __bfloat162float(h));
    }
}

// =========================================================================
// radix-4 Stockham stage; 128 "logical" threads (one warp-group), one
// butterfly each. tid is the within-group thread id (0..127).
// =========================================================================
template<int M, int INV>
__device__ __forceinline__ void r4(const float2* __restrict__ src,
                                   float2* __restrict__ dst,
                                   float2 w1, float2 w2, int tid)
{
    const float w1y = INV ? -w1.y : w1.y;
    const float w2y = INV ? -w2.y : w2.y;
    int k = tid & (M - 1);
    float2 x0 = src[tid], x1 = src[tid+128], x2 = src[tid+256], x3 = src[tid+384];
    float2 a   = make_float2(x0.x + x2.x, x0.y + x2.y);
    float2 s02 = make_float2(x0.x - x2.x, x0.y - x2.y);
    float2 c   = make_float2(x1.x + x3.x, x1.y + x3.y);
    float2 s13 = make_float2(x1.x - x3.x, x1.y - x3.y);
    float2 b = make_float2(w1.x*s02.x - w1y*s02.y, w1.x*s02.y + w1y*s02.x);
    float2 q = INV ? make_float2(-s13.y, s13.x) : make_float2(s13.y, -s13.x);
    float2 d = make_float2(w1.x*q.x - w1y*q.y, w1.x*q.y + w1y*q.x);
    int o = 4*tid - 3*k;
    dst[o]     = make_float2(a.x + c.x, a.y + c.y);
    dst[o + M] = make_float2(b.x + d.x, b.y + d.y);
    float2 ac = make_float2(a.x - c.x, a.y - c.y);
    float2 bd = make_float2(b.x - d.x, b.y - d.y);
    dst[o + 2*M] = make_float2(w2.x*ac.x - w2y*ac.y, w2.x*ac.y + w2y*ac.x);
    dst[o + 3*M] = make_float2(w2.x*bd.x - w2y*bd.y, w2.x*bd.y + w2y*bd.x);
}

template<int INV>
__device__ __forceinline__ void r4_reg(float2 x0, float2 x1, float2 x2, float2 x3,
                                       float2* __restrict__ dst,
                                       float2 w1, float2 w2, int tid)
{
    const float w1y = INV ? -w1.y : w1.y;
    const float w2y = INV ? -w2.y : w2.y;
    float2 a   = make_float2(x0.x + x2.x, x0.y + x2.y);
    float2 s02 = make_float2(x0.x - x2.x, x0.y - x2.y);
    float2 c   = make_float2(x1.x + x3.x, x1.y + x3.y);
    float2 s13 = make_float2(x1.x - x3.x, x1.y - x3.y);
    float2 b = make_float2(w1.x*s02.x - w1y*s02.y, w1.x*s02.y + w1y*s02.x);
    float2 q = INV ? make_float2(-s13.y, s13.x) : make_float2(s13.y, -s13.x);
    float2 d = make_float2(w1.x*q.x - w1y*q.y, w1.x*q.y + w1y*q.x);
    int o = 4*tid;
    dst[o]   = make_float2(a.x + c.x, a.y + c.y);
    dst[o+1] = make_float2(b.x + d.x, b.y + d.y);
    float2 ac = make_float2(a.x - c.x, a.y - c.y);
    float2 bd = make_float2(b.x - d.x, b.y - d.y);
    dst[o+2] = make_float2(w2.x*ac.x - w2y*ac.y, w2.x*ac.y + w2y*ac.x);
    dst[o+3] = make_float2(w2.x*bd.x - w2y*bd.y, w2.x*bd.y + w2y*bd.x);
}

// =========================================================================
// Scan kernel: 256 threads = TWO independent 128-thread warp-groups, each
// running ONE batch row's chain (per-thread state identical to the 1-batch
// version -> no register spill). The two chains share barriers; each SMSP
// holds one warp of each chain, so latency in one chain is hidden by issue
// from the other. 10 syncs per step.
// =========================================================================
__global__ __launch_bounds__(256)
void scan_kernel(const float* __restrict__ h0,
                 const float* __restrict__ b_h,
                 const float* __restrict__ d1,
                 const float* __restrict__ d2,
                 const float* __restrict__ d3,
                 const float* __restrict__ r1re, const float* __restrict__ r1im,
                 const float* __restrict__ r2re, const float* __restrict__ r2im,
                 const int*   __restrict__ perm,
                 float* __restrict__ dout)
{
    __shared__ float2 SA[2][512], SB[2][512];
    __shared__ float2 V1s[512];
    __shared__ float2 RED[2][4];
    __shared__ float  FAC[2];

    const int tidg = threadIdx.x;
    const int g    = tidg >> 7;            // warp-group = which batch chain
    const int tid  = tidg & 127;           // id within group
    const int lane = tid & 31;
    const int wid4 = tid >> 5;             // warp within group (0..3)
    const int b    = blockIdx.x * 2 + g;   // this group's batch row

    float2* const mySA = SA[g];
    float2* const mySB = SB[g];

    // ---- per-thread constants at idx_r = tid + 128r ----
    float2 h[4], e1r[4], e2r[4], e3r[4], v1r[4], v2r[4];
    float bhr[4]; int pr[4];
    #pragma unroll
    for (int r = 0; r < 4; r++) {
        int idx = tid + 128*r;
        float sn, cs;
        sincosf(d1[idx], &sn, &cs); e1r[r] = make_float2(cs, sn);
        sincosf(d2[idx], &sn, &cs); e2r[r] = make_float2(cs, sn);
        sincosf(d3[idx], &sn, &cs); e3r[r] = make_float2(cs, sn);
        v1r[r] = make_float2(r1re[idx], r1im[idx]);
        v2r[r] = make_float2(r2re[idx], r2im[idx]);
        if (g == 0) V1s[idx] = v1r[r];
        bhr[r] = b_h[idx];
        pr[r]  = perm[idx];
        h[r]   = make_float2(h0[b*1024 + idx], h0[b*1024 + 512 + idx]);
    }

    // ---- per-thread twiddles, stages m = 1,4,16,64 ----
    float2 W1[4], W2[4];
    #pragma unroll
    for (int s = 0; s < 4; s++) {
        int m = 1 << (2*s);
        int base = tid & ~(m - 1);
        float sn, cs;
        float a1 = -6.283185307179586f * (float)base / 512.0f;
        sincosf(a1, &sn, &cs); W1[s] = make_float2(cs, sn);
        float a2 = -6.283185307179586f * (float)(2*base) / 512.0f;
        sincosf(a2, &sn, &cs); W2[s] = make_float2(cs, sn);
    }

    // ---- fac1/fac2 = 2/||v||^2 (same for both groups; group 0 computes) ----
    {
        float n1 = 0.f, n2 = 0.f;
        #pragma unroll
        for (int r = 0; r < 4; r++) {
            n1 += v1r[r].x*v1r[r].x + v1r[r].y*v1r[r].y;
            n2 += v2r[r].x*v2r[r].x + v2r[r].y*v2r[r].y;
        }
        #pragma unroll
        for (int off = 16; off; off >>= 1) {
            n1 += __shfl_xor_sync(0xffffffffu, n1, off);
            n2 += __shfl_xor_sync(0xffffffffu, n2, off);
        }
        if (g == 0 && lane == 0) RED[0][wid4] = make_float2(n1, n2);
        __syncthreads();
        if (tidg == 0) {
            float a  = (RED[0][0].x + RED[0][1].x) + (RED[0][2].x + RED[0][3].x);
            float bb = (RED[0][0].y + RED[0][1].y) + (RED[0][2].y + RED[0][3].y);
            FAC[0] = 2.f / a; FAC[1] = 2.f / bb;
        }
        __syncthreads();
    }
    const float fac1 = FAC[0], fac2 = FAC[1];
    const int brow = b * T_;
    const float inv512 = 1.0f / 512.0f;

    for (int t = 0; t < T_; t++) {
        // prefetch u_t
        float2 u0[4];
        {
            const float2* up = g_u + (size_t)(brow + t) * H_;
            #pragma unroll
            for (int r = 0; r < 4; r++) u0[r] = up[tid + 128*r];
        }

        // FFT stage 1 (m=1), fused h*e1, regs -> SA
        r4_reg<0>(cmul(h[0], e1r[0]), cmul(h[1], e1r[1]),
                  cmul(h[2], e1r[2]), cmul(h[3], e1r[3]),
                  mySA, W1[0], W2[0], tid);
        __syncthreads();                                           // 1
        r4<4,  0>(mySA, mySB, W1[1], W2[1], tid); __syncthreads(); // 2
        r4<16, 0>(mySB, mySA, W1[2], W2[2], tid); __syncthreads(); // 3
        r4<64, 0>(mySA, mySB, W1[3], W2[3], tid); __syncthreads(); // 4

        // stage 5: radix-2 m=256, SB -> z -> SA ; dot1 partial
        float2 z[4];
        {
            float2 a0 = mySB[tid],     a1 = mySB[tid+128];
            float2 a2 = mySB[tid+256], a3 = mySB[tid+384];
            z[0] = make_float2(a0.x + a2.x, a0.y + a2.y);
            z[2] = make_float2(a0.x - a2.x, a0.y - a2.y);
            z[1] = make_float2(a1.x + a3.x, a1.y + a3.y);
            z[3] = make_float2(a1.x - a3.x, a1.y - a3.y);
        }
        mySA[tid] = z[0]; mySA[tid+128] = z[1];
        mySA[tid+256] = z[2]; mySA[tid+384] = z[3];
        {
            float dx = 0.f, dy = 0.f;
            #pragma unroll
            for (int r = 0; r < 4; r++) {
                dx += z[r].x*v1r[r].x + z[r].y*v1r[r].y;
                dy += z[r].y*v1r[r].x - z[r].x*v1r[r].y;
            }
            #pragma unroll
            for (int off = 16; off; off >>= 1) {
                dx += __shfl_xor_sync(0xffffffffu, dx, off);
                dy += __shfl_xor_sync(0xffffffffu, dy, off);
            }
            if (lane == 0) RED[g][wid4] = make_float2(dx, dy);
        }
        __syncthreads();                                           // 5
        float2 dot1;
        dot1.x = ((RED[g][0].x + RED[g][1].x) + (RED[g][2].x + RED[g][3].x)) * fac1;
        dot1.y = ((RED[g][0].y + RED[g][1].y) + (RED[g][2].y + RED[g][3].y)) * fac1;

        // IFFT stage 1: fused reflect1 + permute + e2, SA -> SB
        {
            float2 x[4];
            #pragma unroll
            for (int i = 0; i < 4; i++) {
                int p = pr[i];
                float2 zz = mySA[p], vv = V1s[p];
                zz.x -= dot1.x*vv.x - dot1.y*vv.y;
                zz.y -= dot1.x*vv.y + dot1.y*vv.x;
                x[i] = cmul(zz, e2r[i]);
            }
            r4_reg<1>(x[0], x[1], x[2], x[3], mySB, W1[0], W2[0], tid);
        }
        __syncthreads();                                           // 6
        r4<4,  1>(mySB, mySA, W1[1], W2[1], tid); __syncthreads(); // 7
        r4<16, 1>(mySA, mySB, W1[2], W2[2], tid); __syncthreads(); // 8
        r4<64, 1>(mySB, mySA, W1[3], W2[3], tid); __syncthreads(); // 9

        // IFFT stage 5: SA -> z ; dot2 partial
        {
            float2 a0 = mySA[tid],     a1 = mySA[tid+128];
            float2 a2 = mySA[tid+256], a3 = mySA[tid+384];
            z[0] = make_float2(a0.x + a2.x, a0.y + a2.y);
            z[2] = make_float2(a0.x - a2.x, a0.y - a2.y);
            z[1] = make_float2(a1.x + a3.x, a1.y + a3.y);
            z[3] = make_float2(a1.x - a3.x, a1.y - a3.y);
        }
        {
            float dx = 0.f, dy = 0.f;
            #pragma unroll
            for (int r = 0; r < 4; r++) {
                dx += z[r].x*v2r[r].x + z[r].y*v2r[r].y;
                dy += z[r].y*v2r[r].x - z[r].x*v2r[r].y;
            }
            #pragma unroll
            for (int off = 16; off; off >>= 1) {
                dx += __shfl_xor_sync(0xffffffffu, dx, off);
                dy += __shfl_xor_sync(0xffffffffu, dy, off);
            }
            if (lane == 0) RED[g][wid4] = make_float2(dx, dy);
        }
        __syncthreads();                                           // 10
        float2 dot2;
        dot2.x = ((RED[g][0].x + RED[g][1].x) + (RED[g][2].x + RED[g][3].x)) * fac2;
        dot2.y = ((RED[g][0].y + RED[g][1].y) + (RED[g][2].y + RED[g][3].y)) * fac2;

        // epilogue: reflect2 + e3 + 1/512 + u + modReLU (registers only)
        const int orow = (brow + t) * (2*H_);
        #pragma unroll
        for (int r = 0; r < 4; r++) {
            float2 zz = z[r], vv = v2r[r];
            zz.x -= dot2.x*vv.x - dot2.y*vv.y;
            zz.y -= dot2.x*vv.y + dot2.y*vv.x;
            float2 e = e3r[r];
            float2 sv = make_float2((zz.x*e.x - zz.y*e.y) * inv512,
                                    (zz.x*e.y + zz.y*e.x) * inv512);
            float2 pre = make_float2(u0[r].x + sv.x, u0[r].y + sv.y);
            float norm = sqrtf(pre.x*pre.x + pre.y*pre.y);
            float sc = fmaxf(norm + bhr[r], 0.f) / (norm + 1e-6f);
            float2 nw = make_float2(pre.x*sc, pre.y*sc);
            h[r] = nw;
            int idx = tid + 128*r;
            __nv_bfloat16 hx = __float2bfloat16(nw.x);
            __nv_bfloat16 hy = __float2bfloat16(nw.y);
            g_outsH[orow + idx]       = hx;
            g_outsL[orow + idx]       = __float2bfloat16(nw.x - __bfloat162float(hx));
            g_outsH[orow + 512 + idx] = hy;
            g_outsL[orow + 512 + idx] = __float2bfloat16(nw.y - __bfloat162float(hy));
        }
        // next step's first SA write is protected by sync 10
    }

    #pragma unroll
    for (int r = 0; r < 4; r++) {
        int idx = tid + 128*r;
        dout[OUT_OFF + b*1024 + idx]       = h[r].x;
        dout[OUT_OFF + b*1024 + 512 + idx] = h[r].y;
    }
}

// =========================================================================
// bf16x3 GEMM: pre-split operands, cp.async double buffer, ldmatrix frags
// =========================================================================
#define MMA16816(d, a, b)                                                     \
    asm volatile("mma.sync.aligned.m16n8k16.row.col.f32.bf16.bf16.f32 "       \
                 "{%0,%1,%2,%3}, {%4,%5,%6,%7}, {%8,%9}, {%0,%1,%2,%3};\n"    \
                 : "+f"(d[0]), "+f"(d[1]), "+f"(d[2]), "+f"(d[3])             \
                 : "r"(a[0]), "r"(a[1]), "r"(a[2]), "r"(a[3]),                \
                   "r"(b[0]), "r"(b[1]))

#define LDMX4(r0, r1, r2, r3, addr)                                           \
    asm volatile("ldmatrix.sync.aligned.m8n8.x4.shared.b16 {%0,%1,%2,%3}, [%4];" \
                 : "=r"(r0), "=r"(r1), "=r"(r2), "=r"(r3) : "r"(addr))

__device__ __forceinline__ void cp16(void* dst, const void* src) {
    uint32_t d = (uint32_t)__cvta_generic_to_shared(dst);
    asm volatile("cp.async.cg.shared.global [%0], [%1], 16;\n" :: "r"(d), "l"(src));
}

// smem layout (dynamic): As[buf][hl][128][40], Bs[buf][hl][64][40]
#define AS(p, buf, hl, r, c) (p)[((((buf)*2 + (hl))*128 + (r))*40) + (c)]
#define BS(p, buf, hl, r, c) (p)[((((buf)*2 + (hl))*64  + (r))*40) + (c)]
#define GEMM_SMEM ((2*2*128*40 + 2*2*64*40) * 2)   // 61440 bytes

template<int MODE>
__global__ __launch_bounds__(256)
void gemm_bf16s(const float* __restrict__ bias,
                float* __restrict__ C, int M, int N, int K)
{
    extern __shared__ __nv_bfloat16 smem[];
    __nv_bfloat16* Asm = smem;
    __nv_bfloat16* Bsm = smem + 2*2*128*40;

    const __nv_bfloat16* AH = (MODE == 0) ? g_xH : g_outsH;
    const __nv_bfloat16* AL = (MODE == 0) ? g_xL : g_outsL;
    const __nv_bfloat16* WH = (MODE == 0) ? g_w1H : g_w2H;
    const __nv_bfloat16* WL = (MODE == 0) ? g_w1L : g_w2L;

    const int tid = threadIdx.x;
    const int wid = tid >> 5, lane = tid & 31;
    const int wm = wid >> 1, wn = wid & 1;
    const int groupID = lane >> 2, tig = lane & 3;
    const int bm0 = blockIdx.y * 128;
    const int bn0 = blockIdx.x * 64;
    const int KT = K / 32;

    const int ar0 = tid >> 2,         aq0 = (tid & 3) * 8;
    const int ar1 = (tid + 256) >> 2, aq1 = aq0;
    const int br  = tid >> 2,         bq  = (tid & 3) * 8;

    const int a_row = (lane & 15);
    const int a_col = (lane >> 4) * 8;
    const int b_row = ((lane >> 4) << 3) + (lane & 7);
    const int b_col = ((lane >> 3) & 1) * 8;

    float acc[2][4][4];
    #pragma unroll
    for (int mi = 0; mi < 2; mi++)
        #pragma unroll
        for (int ni = 0; ni < 4; ni++)
            #pragma unroll
            for (int j = 0; j < 4; j++) acc[mi][ni][j] = 0.f;

    auto load_tile = [&](int kt, int buf) {
        int k0 = kt * 32;
        cp16(&AS(Asm, buf, 0, ar0, aq0), AH + (size_t)(bm0 + ar0)*K + k0 + aq0);
        cp16(&AS(Asm, buf, 0, ar1, aq1), AH + (size_t)(bm0 + ar1)*K + k0 + aq1);
        cp16(&AS(Asm, buf, 1, ar0, aq0), AL + (size_t)(bm0 + ar0)*K + k0 + aq0);
        cp16(&AS(Asm, buf, 1, ar1, aq1), AL + (size_t)(bm0 + ar1)*K + k0 + aq1);
        cp16(&BS(Bsm, buf, 0, br, bq),   WH + (size_t)(bn0 + br)*K + k0 + bq);
        cp16(&BS(Bsm, buf, 1, br, bq),   WL + (size_t)(bn0 + br)*K + k0 + bq);
    };

    load_tile(0, 0);
    asm volatile("cp.async.commit_group;\n");

    for (int kt = 0; kt < KT; kt++) {
        const int buf = kt & 1;
        if (kt + 1 < KT) {
            load_tile(kt + 1, (kt + 1) & 1);
            asm volatile("cp.async.commit_group;\n");
            asm volatile("cp.async.wait_group 1;\n");
        } else {
            asm volatile("cp.async.wait_group 0;\n");
        }
        __syncthreads();

        #pragma unroll
        for (int kk = 0; kk < 2; kk++) {
            const int kb = kk * 16;
            uint32_t aH[2][4], aL[2][4], bH[4][2], bL[4][2];
            #pragma unroll
            for (int mi = 0; mi < 2; mi++) {
                uint32_t adrH = (uint32_t)__cvta_generic_to_shared(
                    &AS(Asm, buf, 0, wm*32 + mi*16 + a_row, kb + a_col));
                uint32_t adrL = (uint32_t)__cvta_generic_to_shared(
                    &AS(Asm, buf, 1, wm*32 + mi*16 + a_row, kb + a_col));
                LDMX4(aH[mi][0], aH[mi][1], aH[mi][2], aH[mi][3], adrH);
                LDMX4(aL[mi][0], aL[mi][1], aL[mi][2], aL[mi][3], adrL);
            }
            #pragma unroll
            for (int nip = 0; nip < 2; nip++) {
                uint32_t adrH = (uint32_t)__cvta_generic_to_shared(
                    &BS(Bsm, buf, 0, wn*32 + nip*16 + b_row, kb + b_col));
                uint32_t adrL = (uint32_t)__cvta_generic_to_shared(
                    &BS(Bsm, buf, 1, wn*32 + nip*16 + b_row, kb + b_col));
                LDMX4(bH[2*nip][0], bH[2*nip][1], bH[2*nip+1][0], bH[2*nip+1][1], adrH);
                LDMX4(bL[2*nip][0], bL[2*nip][1], bL[2*nip+1][0], bL[2*nip+1][1], adrL);
            }
            #pragma unroll
            for (int mi = 0; mi < 2; mi++)
                #pragma unroll
                for (int ni = 0; ni < 4; ni++) {
                    MMA16816(acc[mi][ni], aH[mi], bH[ni]);
                    MMA16816(acc[mi][ni], aH[mi], bL[ni]);
                    MMA16816(acc[mi][ni], aL[mi], bH[ni]);
                }
        }
        __syncthreads();
    }

    // ---- epilogue ----
    #pragma unroll
    for (int mi = 0; mi < 2; mi++) {
        #pragma unroll
        for (int ni = 0; ni < 4; ni++) {
            int r0 = bm0 + wm*32 + mi*16 + groupID;
            int c0 = bn0 + wn*32 + ni*8 + 2*tig;
            float v00 = acc[mi][ni][0], v01 = acc[mi][ni][1];
            float v10 = acc[mi][ni][2], v11 = acc[mi][ni][3];
            if (MODE == 0) {
                #pragma unroll
                for (int q = 0; q < 4; q++) {
                    int rr = (q < 2) ? r0 : (r0 + 8);
                    int cc = (q & 1) ? (c0 + 1) : c0;
                    float vv = (q==0)?v00:(q==1)?v01:(q==2)?v10:v11;
                    if (cc < 512) g_u[(size_t)rr*512 + cc].x = vv;
                    else          g_u[(size_t)rr*512 + cc - 512].y = vv;
                }
            } else {
                float b0 = bias[c0], b1 = bias[c0 + 1];
                C[(size_t)r0*N + c0]         = v00 + b0;
                C[(size_t)r0*N + c0 + 1]     = v01 + b1;
                C[(size_t)(r0+8)*N + c0]     = v10 + b0;
                C[(size_t)(r0+8)*N + c0 + 1] = v11 + b1;
            }
        }
    }
}

// =========================================================================
extern "C" void kernel_launch(void* const* d_in, const int* in_sizes, int n_in,
                              void* d_out, int out_size)
{
    const float* x    = (const float*)d_in[0];
    const float* h0   = (const float*)d_in[1];
    const float* itoh = (const float*)d_in[2];
    const float* fcw  = (const float*)d_in[3];
    const float* fcb  = (const float*)d_in[4];
    const float* bh   = (const float*)d_in[5];
    const float* d1   = (const float*)d_in[6];
    const float* d2   = (const float*)d_in[7];
    const float* d3   = (const float*)d_in[8];
    const float* r1re = (const float*)d_in[9];
    const float* r1im = (const float*)d_in[10];
    const float* r2re = (const float*)d_in[11];
    const float* r2im = (const float*)d_in[12];
    const int*   perm = (const int*)d_in[13];
    float* out = (float*)d_out;

    cudaFuncSetAttribute(gemm_bf16s<0>, cudaFuncAttributeMaxDynamicSharedMemorySize, GEMM_SMEM);
    cudaFuncSetAttribute(gemm_bf16s<1>, cudaFuncAttributeMaxDynamicSharedMemorySize, GEMM_SMEM);

    {
        int n4 = (MROWS*IN_) / 4;
        split_kernel<0><<<(n4 + 255)/256, 256>>>(x, n4);
        n4 = (2*H_*IN_) / 4;
        split_kernel<1><<<(n4 + 255)/256, 256>>>(itoh, n4);
        n4 = (OUT_*2*H_) / 4;
        split_kernel<2><<<(n4 + 255)/256, 256>>>(fcw, n4);
    }

    // GEMM1: u = x @ itoh^T  (M=32768, N=1024, K=256) -> g_u
    gemm_bf16s<0><<<dim3(1024/64, MROWS/128), 256, GEMM_SMEM>>>(nullptr, nullptr,
                                                                MROWS, 1024, 256);
    // scan: 2 batch chains per CTA, one per 128-thread warp-group
    scan_kernel<<<B_/2, 256>>>(h0, bh, d1, d2, d3, r1re, r1im, r2re, r2im, perm, out);
    // GEMM2: outputs = outs @ fc_w^T + fc_b  (M=32768, N=256, K=1024)
    gemm_bf16s<1><<<dim3(256/64, MROWS/128), 256, GEMM_SMEM>>>(fcb, out,
                                                               MROWS, 256, 1024);
}

// round 5
// speedup vs baseline: 1.2156x; 1.0418x over previous
#include <cuda_runtime.h>
#include <cuda_bf16.h>
#include <cstdint>

#define B_   64
#define T_   512
#define IN_  256
#define OUT_ 256
#define H_   512
#define MROWS (B_*T_)          // 32768
#define OUT_OFF (B_*T_*OUT_)   // 8388608 : offset of "hidden" in d_out

// ---------------- device scratch (no cudaMalloc allowed) ----------------
__device__ __align__(16) float2 g_u[MROWS*H_];                 // 128 MB
__device__ __align__(16) __nv_bfloat16 g_outsH[MROWS*2*H_];    // 64 MB
__device__ __align__(16) __nv_bfloat16 g_outsL[MROWS*2*H_];    // 64 MB
__device__ __align__(16) __nv_bfloat16 g_xH[MROWS*IN_];
__device__ __align__(16) __nv_bfloat16 g_xL[MROWS*IN_];
__device__ __align__(16) __nv_bfloat16 g_w1H[2*H_*IN_];
__device__ __align__(16) __nv_bfloat16 g_w1L[2*H_*IN_];
__device__ __align__(16) __nv_bfloat16 g_w2H[OUT_*2*H_];
__device__ __align__(16) __nv_bfloat16 g_w2L[OUT_*2*H_];

__device__ __forceinline__ float2 cmul(float2 a, float2 b) {
    return make_float2(a.x*b.x - a.y*b.y, a.x*b.y + a.y*b.x);
}

// =========================================================================
// split kernels: fp32 -> (hi, lo) bf16
// =========================================================================
template<int WHICH>
__global__ void split_kernel(const float* __restrict__ src, int n4)
{
    __nv_bfloat16 *hi, *lo;
    if (WHICH == 0) { hi = g_xH;  lo = g_xL;  }
    if (WHICH == 1) { hi = g_w1H; lo = g_w1L; }
    if (WHICH == 2) { hi = g_w2H; lo = g_w2L; }
    int i = blockIdx.x * blockDim.x + threadIdx.x;
    if (i >= n4) return;
    float4 v = ((const float4*)src)[i];
    const float* pv = (const float*)&v;
    #pragma unroll
    for (int j = 0; j < 4; j++) {
        __nv_bfloat16 h = __float2bfloat16(pv[j]);
        hi[4*i + j] = h;
        lo[4*i + j] = __float2bfloat16(pv[j] - __bfloat162float(h));
    }
}

// =========================================================================
// radix-4 Stockham stage; 128 "logical" threads (one warp-group), one
// butterfly each. tid is the within-group thread id (0..127).
// =========================================================================
template<int M, int INV>
__device__ __forceinline__ void r4(const float2* __restrict__ src,
                                   float2* __restrict__ dst,
                                   float2 w1, float2 w2, int tid)
{
    const float w1y = INV ? -w1.y : w1.y;
    const float w2y = INV ? -w2.y : w2.y;
    int k = tid & (M - 1);
    float2 x0 = src[tid], x1 = src[tid+128], x2 = src[tid+256], x3 = src[tid+384];
    float2 a   = make_float2(x0.x + x2.x, x0.y + x2.y);
    float2 s02 = make_float2(x0.x - x2.x, x0.y - x2.y);
    float2 c   = make_float2(x1.x + x3.x, x1.y + x3.y);
    float2 s13 = make_float2(x1.x - x3.x, x1.y - x3.y);
    float2 b = make_float2(w1.x*s02.x - w1y*s02.y, w1.x*s02.y + w1y*s02.x);
    float2 q = INV ? make_float2(-s13.y, s13.x) : make_float2(s13.y, -s13.x);
    float2 d = make_float2(w1.x*q.x - w1y*q.y, w1.x*q.y + w1y*q.x);
    int o = 4*tid - 3*k;
    dst[o]     = make_float2(a.x + c.x, a.y + c.y);
    dst[o + M] = make_float2(b.x + d.x, b.y + d.y);
    float2 ac = make_float2(a.x - c.x, a.y - c.y);
    float2 bd = make_float2(b.x - d.x, b.y - d.y);
    dst[o + 2*M] = make_float2(w2.x*ac.x - w2y*ac.y, w2.x*ac.y + w2y*ac.x);
    dst[o + 3*M] = make_float2(w2.x*bd.x - w2y*bd.y, w2.x*bd.y + w2y*bd.x);
}

template<int INV>
__device__ __forceinline__ void r4_reg(float2 x0, float2 x1, float2 x2, float2 x3,
                                       float2* __restrict__ dst,
                                       float2 w1, float2 w2, int tid)
{
    const float w1y = INV ? -w1.y : w1.y;
    const float w2y = INV ? -w2.y : w2.y;
    float2 a   = make_float2(x0.x + x2.x, x0.y + x2.y);
    float2 s02 = make_float2(x0.x - x2.x, x0.y - x2.y);
    float2 c   = make_float2(x1.x + x3.x, x1.y + x3.y);
    float2 s13 = make_float2(x1.x - x3.x, x1.y - x3.y);
    float2 b = make_float2(w1.x*s02.x - w1y*s02.y, w1.x*s02.y + w1y*s02.x);
    float2 q = INV ? make_float2(-s13.y, s13.x) : make_float2(s13.y, -s13.x);
    float2 d = make_float2(w1.x*q.x - w1y*q.y, w1.x*q.y + w1y*q.x);
    int o = 4*tid;
    dst[o]   = make_float2(a.x + c.x, a.y + c.y);
    dst[o+1] = make_float2(b.x + d.x, b.y + d.y);
    float2 ac = make_float2(a.x - c.x, a.y - c.y);
    float2 bd = make_float2(b.x - d.x, b.y - d.y);
    dst[o+2] = make_float2(w2.x*ac.x - w2y*ac.y, w2.x*ac.y + w2y*ac.x);
    dst[o+3] = make_float2(w2.x*bd.x - w2y*bd.y, w2.x*bd.y + w2y*bd.x);
}

// =========================================================================
// Scan kernel: 256 threads = TWO independent 128-thread warp-groups, each
// running ONE batch row's chain (per-thread state identical to the 1-batch
// version -> no register spill). The two chains share barriers; each SMSP
// holds one warp of each chain, so latency in one chain is hidden by issue
// from the other. 10 syncs per step.
// =========================================================================
__global__ __launch_bounds__(256)
void scan_kernel(const float* __restrict__ h0,
                 const float* __restrict__ b_h,
                 const float* __restrict__ d1,
                 const float* __restrict__ d2,
                 const float* __restrict__ d3,
                 const float* __restrict__ r1re, const float* __restrict__ r1im,
                 const float* __restrict__ r2re, const float* __restrict__ r2im,
                 const int*   __restrict__ perm,
                 float* __restrict__ dout)
{
    __shared__ float2 SA[2][512], SB[2][512];
    __shared__ float2 V1s[512];
    __shared__ float2 RED[2][4];
    __shared__ float  FAC[2];

    const int tidg = threadIdx.x;
    const int g    = tidg >> 7;            // warp-group = which batch chain
    const int tid  = tidg & 127;           // id within group
    const int lane = tid & 31;
    const int wid4 = tid >> 5;             // warp within group (0..3)
    const int b    = blockIdx.x * 2 + g;   // this group's batch row

    float2* const mySA = SA[g];
    float2* const mySB = SB[g];

    // ---- per-thread constants at idx_r = tid + 128r ----
    float2 h[4], e1r[4], e2r[4], e3r[4], v1r[4], v2r[4];
    float bhr[4]; int pr[4];
    #pragma unroll
    for (int r = 0; r < 4; r++) {
        int idx = tid + 128*r;
        float sn, cs;
        sincosf(d1[idx], &sn, &cs); e1r[r] = make_float2(cs, sn);
        sincosf(d2[idx], &sn, &cs); e2r[r] = make_float2(cs, sn);
        sincosf(d3[idx], &sn, &cs); e3r[r] = make_float2(cs, sn);
        v1r[r] = make_float2(r1re[idx], r1im[idx]);
        v2r[r] = make_float2(r2re[idx], r2im[idx]);
        if (g == 0) V1s[idx] = v1r[r];
        bhr[r] = b_h[idx];
        pr[r]  = perm[idx];
        h[r]   = make_float2(h0[b*1024 + idx], h0[b*1024 + 512 + idx]);
    }

    // ---- per-thread twiddles, stages m = 1,4,16,64 ----
    float2 W1[4], W2[4];
    #pragma unroll
    for (int s = 0; s < 4; s++) {
        int m = 1 << (2*s);
        int base = tid & ~(m - 1);
        float sn, cs;
        float a1 = -6.283185307179586f * (float)base / 512.0f;
        sincosf(a1, &sn, &cs); W1[s] = make_float2(cs, sn);
        float a2 = -6.283185307179586f * (float)(2*base) / 512.0f;
        sincosf(a2, &sn, &cs); W2[s] = make_float2(cs, sn);
    }

    // ---- fac1/fac2 = 2/||v||^2 (same for both groups; group 0 computes) ----
    {
        float n1 = 0.f, n2 = 0.f;
        #pragma unroll
        for (int r = 0; r < 4; r++) {
            n1 += v1r[r].x*v1r[r].x + v1r[r].y*v1r[r].y;
            n2 += v2r[r].x*v2r[r].x + v2r[r].y*v2r[r].y;
        }
        #pragma unroll
        for (int off = 16; off; off >>= 1) {
            n1 += __shfl_xor_sync(0xffffffffu, n1, off);
            n2 += __shfl_xor_sync(0xffffffffu, n2, off);
        }
        if (g == 0 && lane == 0) RED[0][wid4] = make_float2(n1, n2);
        __syncthreads();
        if (tidg == 0) {
            float a  = (RED[0][0].x + RED[0][1].x) + (RED[0][2].x + RED[0][3].x);
            float bb = (RED[0][0].y + RED[0][1].y) + (RED[0][2].y + RED[0][3].y);
            FAC[0] = 2.f / a; FAC[1] = 2.f / bb;
        }
        __syncthreads();
    }
    const float fac1 = FAC[0], fac2 = FAC[1];
    const int brow = b * T_;
    const float inv512 = 1.0f / 512.0f;

    for (int t = 0; t < T_; t++) {
        // prefetch u_t
        float2 u0[4];
        {
            const float2* up = g_u + (size_t)(brow + t) * H_;
            #pragma unroll
            for (int r = 0; r < 4; r++) u0[r] = up[tid + 128*r];
        }

        // FFT stage 1 (m=1), fused h*e1, regs -> SA
        r4_reg<0>(cmul(h[0], e1r[0]), cmul(h[1], e1r[1]),
                  cmul(h[2], e1r[2]), cmul(h[3], e1r[3]),
                  mySA, W1[0], W2[0], tid);
        __syncthreads();                                           // 1
        r4<4,  0>(mySA, mySB, W1[1], W2[1], tid); __syncthreads(); // 2
        r4<16, 0>(mySB, mySA, W1[2], W2[2], tid); __syncthreads(); // 3
        r4<64, 0>(mySA, mySB, W1[3], W2[3], tid); __syncthreads(); // 4

        // stage 5: radix-2 m=256, SB -> z -> SA ; dot1 partial
        float2 z[4];
        {
            float2 a0 = mySB[tid],     a1 = mySB[tid+128];
            float2 a2 = mySB[tid+256], a3 = mySB[tid+384];
            z[0] = make_float2(a0.x + a2.x, a0.y + a2.y);
            z[2] = make_float2(a0.x - a2.x, a0.y - a2.y);
            z[1] = make_float2(a1.x + a3.x, a1.y + a3.y);
            z[3] = make_float2(a1.x - a3.x, a1.y - a3.y);
        }
        mySA[tid] = z[0]; mySA[tid+128] = z[1];
        mySA[tid+256] = z[2]; mySA[tid+384] = z[3];
        {
            float dx = 0.f, dy = 0.f;
            #pragma unroll
            for (int r = 0; r < 4; r++) {
                dx += z[r].x*v1r[r].x + z[r].y*v1r[r].y;
                dy += z[r].y*v1r[r].x - z[r].x*v1r[r].y;
            }
            #pragma unroll
            for (int off = 16; off; off >>= 1) {
                dx += __shfl_xor_sync(0xffffffffu, dx, off);
                dy += __shfl_xor_sync(0xffffffffu, dy, off);
            }
            if (lane == 0) RED[g][wid4] = make_float2(dx, dy);
        }
        __syncthreads();                                           // 5
        float2 dot1;
        dot1.x = ((RED[g][0].x + RED[g][1].x) + (RED[g][2].x + RED[g][3].x)) * fac1;
        dot1.y = ((RED[g][0].y + RED[g][1].y) + (RED[g][2].y + RED[g][3].y)) * fac1;

        // IFFT stage 1: fused reflect1 + permute + e2, SA -> SB
        {
            float2 x[4];
            #pragma unroll
            for (int i = 0; i < 4; i++) {
                int p = pr[i];
                float2 zz = mySA[p], vv = V1s[p];
                zz.x -= dot1.x*vv.x - dot1.y*vv.y;
                zz.y -= dot1.x*vv.y + dot1.y*vv.x;
                x[i] = cmul(zz, e2r[i]);
            }
            r4_reg<1>(x[0], x[1], x[2], x[3], mySB, W1[0], W2[0], tid);
        }
        __syncthreads();                                           // 6
        r4<4,  1>(mySB, mySA, W1[1], W2[1], tid); __syncthreads(); // 7
        r4<16, 1>(mySA, mySB, W1[2], W2[2], tid); __syncthreads(); // 8
        r4<64, 1>(mySB, mySA, W1[3], W2[3], tid); __syncthreads(); // 9

        // IFFT stage 5: SA -> z ; dot2 partial
        {
            float2 a0 = mySA[tid],     a1 = mySA[tid+128];
            float2 a2 = mySA[tid+256], a3 = mySA[tid+384];
            z[0] = make_float2(a0.x + a2.x, a0.y + a2.y);
            z[2] = make_float2(a0.x - a2.x, a0.y - a2.y);
            z[1] = make_float2(a1.x + a3.x, a1.y + a3.y);
            z[3] = make_float2(a1.x - a3.x, a1.y - a3.y);
        }
        {
            float dx = 0.f, dy = 0.f;
            #pragma unroll
            for (int r = 0; r < 4; r++) {
                dx += z[r].x*v2r[r].x + z[r].y*v2r[r].y;
                dy += z[r].y*v2r[r].x - z[r].x*v2r[r].y;
            }
            #pragma unroll
            for (int off = 16; off; off >>= 1) {
                dx += __shfl_xor_sync(0xffffffffu, dx, off);
                dy += __shfl_xor_sync(0xffffffffu, dy, off);
            }
            if (lane == 0) RED[g][wid4] = make_float2(dx, dy);
        }
        __syncthreads();                                           // 10
        float2 dot2;
        dot2.x = ((RED[g][0].x + RED[g][1].x) + (RED[g][2].x + RED[g][3].x)) * fac2;
        dot2.y = ((RED[g][0].y + RED[g][1].y) + (RED[g][2].y + RED[g][3].y)) * fac2;

        // epilogue: reflect2 + e3 + 1/512 + u + modReLU (registers only)
        const int orow = (brow + t) * (2*H_);
        #pragma unroll
        for (int r = 0; r < 4; r++) {
            float2 zz = z[r], vv = v2r[r];
            zz.x -= dot2.x*vv.x - dot2.y*vv.y;
            zz.y -= dot2.x*vv.y + dot2.y*vv.x;
            float2 e = e3r[r];
            float2 sv = make_float2((zz.x*e.x - zz.y*e.y) * inv512,
                                    (zz.x*e.y + zz.y*e.x) * inv512);
            float2 pre = make_float2(u0[r].x + sv.x, u0[r].y + sv.y);
            float norm = sqrtf(pre.x*pre.x + pre.y*pre.y);
            float sc = fmaxf(norm + bhr[r], 0.f) / (norm + 1e-6f);
            float2 nw = make_float2(pre.x*sc, pre.y*sc);
            h[r] = nw;
            int idx = tid + 128*r;
            __nv_bfloat16 hx = __float2bfloat16(nw.x);
            __nv_bfloat16 hy = __float2bfloat16(nw.y);
            g_outsH[orow + idx]       = hx;
            g_outsL[orow + idx]       = __float2bfloat16(nw.x - __bfloat162float(hx));
            g_outsH[orow + 512 + idx] = hy;
            g_outsL[orow + 512 + idx] = __float2bfloat16(nw.y - __bfloat162float(hy));
        }
        // next step's first SA write is protected by sync 10
    }

    #pragma unroll
    for (int r = 0; r < 4; r++) {
        int idx = tid + 128*r;
        dout[OUT_OFF + b*1024 + idx]       = h[r].x;
        dout[OUT_OFF + b*1024 + 512 + idx] = h[r].y;
    }
}

// =========================================================================
// bf16x3 GEMM: pre-split operands, cp.async double buffer, ldmatrix frags
// =========================================================================
#define MMA16816(d, a, b)                                                     \
    asm volatile("mma.sync.aligned.m16n8k16.row.col.f32.bf16.bf16.f32 "       \
                 "{%0,%1,%2,%3}, {%4,%5,%6,%7}, {%8,%9}, {%0,%1,%2,%3};\n"    \
                 : "+f"(d[0]), "+f"(d[1]), "+f"(d[2]), "+f"(d[3])             \
                 : "r"(a[0]), "r"(a[1]), "r"(a[2]), "r"(a[3]),                \
                   "r"(b[0]), "r"(b[1]))

#define LDMX4(r0, r1, r2, r3, addr)                                           \
    asm volatile("ldmatrix.sync.aligned.m8n8.x4.shared.b16 {%0,%1,%2,%3}, [%4];" \
                 : "=r"(r0), "=r"(r1), "=r"(r2), "=r"(r3) : "r"(addr))

__device__ __forceinline__ void cp16(void* dst, const void* src) {
    uint32_t d = (uint32_t)__cvta_generic_to_shared(dst);
    asm volatile("cp.async.cg.shared.global [%0], [%1], 16;\n" :: "r"(d), "l"(src));
}

// smem layout (dynamic): As[buf][hl][128][40], Bs[buf][hl][64][40]
#define AS(p, buf, hl, r, c) (p)[((((buf)*2 + (hl))*128 + (r))*40) + (c)]
#define BS(p, buf, hl, r, c) (p)[((((buf)*2 + (hl))*64  + (r))*40) + (c)]
#define GEMM_SMEM ((2*2*128*40 + 2*2*64*40) * 2)   // 61440 bytes

template<int MODE>
__global__ __launch_bounds__(256)
void gemm_bf16s(const float* __restrict__ bias,
                float* __restrict__ C, int M, int N, int K)
{
    extern __shared__ __nv_bfloat16 smem[];
    __nv_bfloat16* Asm = smem;
    __nv_bfloat16* Bsm = smem + 2*2*128*40;

    const __nv_bfloat16* AH = (MODE == 0) ? g_xH : g_outsH;
    const __nv_bfloat16* AL = (MODE == 0) ? g_xL : g_outsL;
    const __nv_bfloat16* WH = (MODE == 0) ? g_w1H : g_w2H;
    const __nv_bfloat16* WL = (MODE == 0) ? g_w1L : g_w2L;

    const int tid = threadIdx.x;
    const int wid = tid >> 5, lane = tid & 31;
    const int wm = wid >> 1, wn = wid & 1;
    const int groupID = lane >> 2, tig = lane & 3;
    const int bm0 = blockIdx.y * 128;
    const int bn0 = blockIdx.x * 64;
    const int KT = K / 32;

    const int ar0 = tid >> 2,         aq0 = (tid & 3) * 8;
    const int ar1 = (tid + 256) >> 2, aq1 = aq0;
    const int br  = tid >> 2,         bq  = (tid & 3) * 8;

    const int a_row = (lane & 15);
    const int a_col = (lane >> 4) * 8;
    const int b_row = ((lane >> 4) << 3) + (lane & 7);
    const int b_col = ((lane >> 3) & 1) * 8;

    float acc[2][4][4];
    #pragma unroll
    for (int mi = 0; mi < 2; mi++)
        #pragma unroll
        for (int ni = 0; ni < 4; ni++)
            #pragma unroll
            for (int j = 0; j < 4; j++) acc[mi][ni][j] = 0.f;

    auto load_tile = [&](int kt, int buf) {
        int k0 = kt * 32;
        cp16(&AS(Asm, buf, 0, ar0, aq0), AH + (size_t)(bm0 + ar0)*K + k0 + aq0);
        cp16(&AS(Asm, buf, 0, ar1, aq1), AH + (size_t)(bm0 + ar1)*K + k0 + aq1);
        cp16(&AS(Asm, buf, 1, ar0, aq0), AL + (size_t)(bm0 + ar0)*K + k0 + aq0);
        cp16(&AS(Asm, buf, 1, ar1, aq1), AL + (size_t)(bm0 + ar1)*K + k0 + aq1);
        cp16(&BS(Bsm, buf, 0, br, bq),   WH + (size_t)(bn0 + br)*K + k0 + bq);
        cp16(&BS(Bsm, buf, 1, br, bq),   WL + (size_t)(bn0 + br)*K + k0 + bq);
    };

    load_tile(0, 0);
    asm volatile("cp.async.commit_group;\n");

    for (int kt = 0; kt < KT; kt++) {
        const int buf = kt & 1;
        if (kt + 1 < KT) {
            load_tile(kt + 1, (kt + 1) & 1);
            asm volatile("cp.async.commit_group;\n");
            asm volatile("cp.async.wait_group 1;\n");
        } else {
            asm volatile("cp.async.wait_group 0;\n");
        }
        __syncthreads();

        #pragma unroll
        for (int kk = 0; kk < 2; kk++) {
            const int kb = kk * 16;
            uint32_t aH[2][4], aL[2][4], bH[4][2], bL[4][2];
            #pragma unroll
            for (int mi = 0; mi < 2; mi++) {
                uint32_t adrH = (uint32_t)__cvta_generic_to_shared(
                    &AS(Asm, buf, 0, wm*32 + mi*16 + a_row, kb + a_col));
                uint32_t adrL = (uint32_t)__cvta_generic_to_shared(
                    &AS(Asm, buf, 1, wm*32 + mi*16 + a_row, kb + a_col));
                LDMX4(aH[mi][0], aH[mi][1], aH[mi][2], aH[mi][3], adrH);
                LDMX4(aL[mi][0], aL[mi][1], aL[mi][2], aL[mi][3], adrL);
            }
            #pragma unroll
            for (int nip = 0; nip < 2; nip++) {
                uint32_t adrH = (uint32_t)__cvta_generic_to_shared(
                    &BS(Bsm, buf, 0, wn*32 + nip*16 + b_row, kb + b_col));
                uint32_t adrL = (uint32_t)__cvta_generic_to_shared(
                    &BS(Bsm, buf, 1, wn*32 + nip*16 + b_row, kb + b_col));
                LDMX4(bH[2*nip][0], bH[2*nip][1], bH[2*nip+1][0], bH[2*nip+1][1], adrH);
                LDMX4(bL[2*nip][0], bL[2*nip][1], bL[2*nip+1][0], bL[2*nip+1][1], adrL);
            }
            #pragma unroll
            for (int mi = 0; mi < 2; mi++)
                #pragma unroll
                for (int ni = 0; ni < 4; ni++) {
                    MMA16816(acc[mi][ni], aH[mi], bH[ni]);
                    MMA16816(acc[mi][ni], aH[mi], bL[ni]);
                    MMA16816(acc[mi][ni], aL[mi], bH[ni]);
                }
        }
        __syncthreads();
    }

    // ---- epilogue ----
    #pragma unroll
    for (int mi = 0; mi < 2; mi++) {
        #pragma unroll
        for (int ni = 0; ni < 4; ni++) {
            int r0 = bm0 + wm*32 + mi*16 + groupID;
            int c0 = bn0 + wn*32 + ni*8 + 2*tig;
            float v00 = acc[mi][ni][0], v01 = acc[mi][ni][1];
            float v10 = acc[mi][ni][2], v11 = acc[mi][ni][3];
            if (MODE == 0) {
                #pragma unroll
                for (int q = 0; q < 4; q++) {
                    int rr = (q < 2) ? r0 : (r0 + 8);
                    int cc = (q & 1) ? (c0 + 1) : c0;
                    float vv = (q==0)?v00:(q==1)?v01:(q==2)?v10:v11;
                    if (cc < 512) g_u[(size_t)rr*512 + cc].x = vv;
                    else          g_u[(size_t)rr*512 + cc - 512].y = vv;
                }
            } else {
                float b0 = bias[c0], b1 = bias[c0 + 1];
                C[(size_t)r0*N + c0]         = v00 + b0;
                C[(size_t)r0*N + c0 + 1]     = v01 + b1;
                C[(size_t)(r0+8)*N + c0]     = v10 + b0;
                C[(size_t)(r0+8)*N + c0 + 1] = v11 + b1;
            }
        }
    }
}

// =========================================================================
extern "C" void kernel_launch(void* const* d_in, const int* in_sizes, int n_in,
                              void* d_out, int out_size)
{
    const float* x    = (const float*)d_in[0];
    const float* h0   = (const float*)d_in[1];
    const float* itoh = (const float*)d_in[2];
    const float* fcw  = (const float*)d_in[3];
    const float* fcb  = (const float*)d_in[4];
    const float* bh   = (const float*)d_in[5];
    const float* d1   = (const float*)d_in[6];
    const float* d2   = (const float*)d_in[7];
    const float* d3   = (const float*)d_in[8];
    const float* r1re = (const float*)d_in[9];
    const float* r1im = (const float*)d_in[10];
    const float* r2re = (const float*)d_in[11];
    const float* r2im = (const float*)d_in[12];
    const int*   perm = (const int*)d_in[13];
    float* out = (float*)d_out;

    cudaFuncSetAttribute(gemm_bf16s<0>, cudaFuncAttributeMaxDynamicSharedMemorySize, GEMM_SMEM);
    cudaFuncSetAttribute(gemm_bf16s<1>, cudaFuncAttributeMaxDynamicSharedMemorySize, GEMM_SMEM);

    {
        int n4 = (MROWS*IN_) / 4;
        split_kernel<0><<<(n4 + 255)/256, 256>>>(x, n4);
        n4 = (2*H_*IN_) / 4;
        split_kernel<1><<<(n4 + 255)/256, 256>>>(itoh, n4);
        n4 = (OUT_*2*H_) / 4;
        split_kernel<2><<<(n4 + 255)/256, 256>>>(fcw, n4);
    }

    // GEMM1: u = x @ itoh^T  (M=32768, N=1024, K=256) -> g_u
    gemm_bf16s<0><<<dim3(1024/64, MROWS/128), 256, GEMM_SMEM>>>(nullptr, nullptr,
                                                                MROWS, 1024, 256);
    // scan: 2 batch chains per CTA, one per 128-thread warp-group
    scan_kernel<<<B_/2, 256>>>(h0, bh, d1, d2, d3, r1re, r1im, r2re, r2im, perm, out);
    // GEMM2: outputs = outs @ fc_w^T + fc_b  (M=32768, N=256, K=1024)
    gemm_bf16s<1><<<dim3(256/64, MROWS/128), 256, GEMM_SMEM>>>(fcb, out,
                                                               MROWS, 256, 1024);
}

// round 6
// speedup vs baseline: 1.4296x; 1.1761x over previous
#include <cuda_runtime.h>
#include <cuda_bf16.h>
#include <cstdint>

#define B_   64
#define T_   512
#define IN_  256
#define OUT_ 256
#define H_   512
#define MROWS (B_*T_)
#define OUT_OFF (B_*T_*OUT_)

__device__ __align__(16) float2 g_u[MROWS*H_];
__device__ __align__(16) __nv_bfloat16 g_outsH[MROWS*2*H_];
__device__ __align__(16) __nv_bfloat16 g_outsL[MROWS*2*H_];
__device__ __align__(16) __nv_bfloat16 g_xH[MROWS*IN_];
__device__ __align__(16) __nv_bfloat16 g_xL[MROWS*IN_];
__device__ __align__(16) __nv_bfloat16 g_w1H[2*H_*IN_];
__device__ __align__(16) __nv_bfloat16 g_w1L[2*H_*IN_];
__device__ __align__(16) __nv_bfloat16 g_w2H[OUT_*2*H_];
__device__ __align__(16) __nv_bfloat16 g_w2L[OUT_*2*H_];

__device__ __forceinline__ float2 cadd(float2 a, float2 b){return make_float2(a.x+b.x, a.y+b.y);}
__device__ __forceinline__ float2 csub(float2 a, float2 b){return make_float2(a.x-b.x, a.y-b.y);}
__device__ __forceinline__ float2 cmul(float2 a, float2 b){return make_float2(a.x*b.x-a.y*b.y, a.x*b.y+a.y*b.x);}
__device__ __forceinline__ float2 cmulc(float2 a, float2 b){return make_float2(a.x*b.x+a.y*b.y, a.y*b.x-a.x*b.y);}
__device__ __forceinline__ float2 mulpi(float2 a){return make_float2(-a.y, a.x);}
__device__ __forceinline__ float2 mulmi(float2 a){return make_float2(a.y, -a.x);}

template<int WHICH>
__global__ void split_kernel(const float* __restrict__ src, int n4)
{
    __nv_bfloat16 *hi, *lo;
    if (WHICH == 0) { hi = g_xH;  lo = g_xL;  }
    if (WHICH == 1) { hi = g_w1H; lo = g_w1L; }
    if (WHICH == 2) { hi = g_w2H; lo = g_w2L; }
    int i = blockIdx.x * blockDim.x + threadIdx.x;
    if (i >= n4) return;
    float4 v = ((const float4*)src)[i];
    const float* pv = (const float*)&v;
    #pragma unroll
    for (int j = 0; j < 4; j++) {
        __nv_bfloat16 h = __float2bfloat16(pv[j]);
        hi[4*i + j] = h;
        lo[4*i + j] = __float2bfloat16(pv[j] - __bfloat162float(h));
    }
}

// DFT-4 over 4 registers. Forward W4=-i; inverse conj.
template<int INV>
__device__ __forceinline__ void dft4(float2& x0, float2& x1, float2& x2, float2& x3)
{
    float2 t0 = cadd(x0, x2), t2 = csub(x0, x2);
    float2 t1 = cadd(x1, x3), t3 = csub(x1, x3);
    float2 a1 = INV ? mulpi(t3) : mulmi(t3);
    float2 a3 = INV ? mulmi(t3) : mulpi(t3);
    x0 = cadd(t0, t1);
    x1 = cadd(t2, a1);
    x2 = csub(t0, t1);
    x3 = cadd(t2, a3);
}

// DIF radix-2 FFT-32 across lanes on 4 regs; output at lane l = comp rev5(l).
template<int INV>
__device__ __forceinline__ void fft32(float2 y[4], const float2 tw32[5], int lane)
{
    #pragma unroll
    for (int s = 0; s < 5; s++) {
        const int st = 16 >> s;
        const bool hi = (lane & st) != 0;
        const float2 tw = tw32[s];
        #pragma unroll
        for (int j = 0; j < 4; j++) {
            float2 v = y[j], pv;
            pv.x = __shfl_xor_sync(0xffffffffu, v.x, st);
            pv.y = __shfl_xor_sync(0xffffffffu, v.y, st);
            float2 sum = cadd(v, pv);
            float2 dif = csub(pv, v);            // a_low - a_high when hi
            float2 tv  = INV ? cmulc(dif, tw) : cmul(dif, tw);
            y[j] = hi ? tv : sum;
        }
    }
}

// =========================================================================
// Scan: 1 chain/CTA, 128 thr. FFT-512 = DIT 4(regs) x [4(regs) x 32(lanes)].
// Owned index after FFT: idx = w + 4j + 16*rev5(lane). 6 syncs/step.
// =========================================================================
__global__ __launch_bounds__(128)
void scan_kernel(const float* __restrict__ h0,
                 const float* __restrict__ b_h,
                 const float* __restrict__ d1,
                 const float* __restrict__ d2,
                 const float* __restrict__ d3,
                 const float* __restrict__ r1re, const float* __restrict__ r1im,
                 const float* __restrict__ r2re, const float* __restrict__ r2im,
                 const int*   __restrict__ perm,
                 float* __restrict__ dout)
{
    __shared__ float2 SA[544], SB[544];
    __shared__ float2 V1o[544], V2o[544];
    __shared__ float2 RED1[4], RED2[4];
    __shared__ float  FAC[2];

    const int b    = blockIdx.x;
    const int tid  = threadIdx.x;
    const int lane = tid & 31;
    const int w    = tid >> 5;
    const int R    = __brev(lane) >> 27;     // rev5(lane)

    int oaddr[4];
    #pragma unroll
    for (int j = 0; j < 4; j++) oaddr[j] = R*17 + w + 4*j;

    float2 h[4], e1r[4], e2r[4], e3r[4];
    float bhr[4]; int paddr[4];
    const float inv512 = 1.0f / 512.0f;
    #pragma unroll
    for (int r = 0; r < 4; r++) {
        int idx = tid + 128*r;
        float sn, cs;
        sincosf(d1[idx], &sn, &cs); e1r[r] = make_float2(cs, sn);
        sincosf(d2[idx], &sn, &cs); e2r[r] = make_float2(cs, sn);
        sincosf(d3[idx], &sn, &cs); e3r[r] = make_float2(cs*inv512, sn*inv512);
        bhr[r] = b_h[idx];
        int p = perm[idx];
        paddr[r] = (p >> 4)*17 + (p & 15);
        h[r] = make_float2(h0[b*1024 + idx], h0[b*1024 + 512 + idx]);
    }
    for (int i = tid; i < 512; i += 128) {
        int a = (i >> 4)*17 + (i & 15);
        V1o[a] = make_float2(r1re[i], r1im[i]);
        V2o[a] = make_float2(r2re[i], r2im[i]);
    }

    const float TWO_PI = 6.283185307179586f;
    float2 c512[3], d128[3], tw32c[5];
    #pragma unroll
    for (int k = 1; k <= 3; k++) {
        float sn, cs;
        sincosf(-TWO_PI * (float)(tid*k) / 512.0f, &sn, &cs);
        c512[k-1] = make_float2(cs, sn);
        sincosf(-TWO_PI * (float)(lane*k) / 128.0f, &sn, &cs);
        d128[k-1] = make_float2(cs, sn);
    }
    #pragma unroll
    for (int s = 0; s < 5; s++) {
        int st = 16 >> s;
        int e  = (lane & (st - 1)) << s;
        float sn, cs;
        sincosf(-TWO_PI * (float)e / 32.0f, &sn, &cs);
        tw32c[s] = make_float2(cs, sn);
    }

    {   // fac1/fac2 = 2/||v||^2
        float n1 = 0.f, n2 = 0.f;
        #pragma unroll
        for (int r = 0; r < 4; r++) {
            int idx = tid + 128*r;
            n1 += r1re[idx]*r1re[idx] + r1im[idx]*r1im[idx];
            n2 += r2re[idx]*r2re[idx] + r2im[idx]*r2im[idx];
        }
        #pragma unroll
        for (int off = 16; off; off >>= 1) {
            n1 += __shfl_xor_sync(0xffffffffu, n1, off);
            n2 += __shfl_xor_sync(0xffffffffu, n2, off);
        }
        if (lane == 0) RED1[w] = make_float2(n1, n2);
        __syncthreads();
        if (tid == 0) {
            float a  = (RED1[0].x + RED1[1].x) + (RED1[2].x + RED1[3].x);
            float bb = (RED1[0].y + RED1[1].y) + (RED1[2].y + RED1[3].y);
            FAC[0] = 2.f / a; FAC[1] = 2.f / bb;
        }
        __syncthreads();
    }
    const float fac1 = FAC[0], fac2 = FAC[1];
    const int brow = b * T_;

    for (int t = 0; t < T_; t++) {
        float2 u0[4];
        {
            const float2* up = g_u + (size_t)(brow + t) * H_;
            #pragma unroll
            for (int r = 0; r < 4; r++) u0[r] = up[tid + 128*r];
        }

        // ph1: forward FFT-512
        float2 y[4];
        #pragma unroll
        for (int r = 0; r < 4; r++) y[r] = cmul(h[r], e1r[r]);
        dft4<0>(y[0], y[1], y[2], y[3]);
        y[1] = cmul(y[1], c512[0]);
        y[2] = cmul(y[2], c512[1]);
        y[3] = cmul(y[3], c512[2]);
        #pragma unroll
        for (int r = 0; r < 4; r++) SA[r*128 + tid] = y[r];
        __syncthreads();                                              // 1
        #pragma unroll
        for (int q = 0; q < 4; q++) y[q] = SA[w*128 + 32*q + lane];
        dft4<0>(y[0], y[1], y[2], y[3]);
        y[1] = cmul(y[1], d128[0]);
        y[2] = cmul(y[2], d128[1]);
        y[3] = cmul(y[3], d128[2]);
        fft32<0>(y, tw32c, lane);                 // now owned order

        // ph2: dot1 + reflect1 in owned space
        float2 v1v[4];
        {
            float dx = 0.f, dy = 0.f;
            #pragma unroll
            for (int j = 0; j < 4; j++) {
                v1v[j] = V1o[oaddr[j]];
                dx += y[j].x*v1v[j].x + y[j].y*v1v[j].y;
                dy += y[j].y*v1v[j].x - y[j].x*v1v[j].y;
            }
            #pragma unroll
            for (int off = 16; off; off >>= 1) {
                dx += __shfl_xor_sync(0xffffffffu, dx, off);
                dy += __shfl_xor_sync(0xffffffffu, dy, off);
            }
            if (lane == 0) RED1[w] = make_float2(dx, dy);
        }
        __syncthreads();                                              // 2
        {
            float2 d;
            d.x = ((RED1[0].x + RED1[1].x) + (RED1[2].x + RED1[3].x)) * fac1;
            d.y = ((RED1[0].y + RED1[1].y) + (RED1[2].y + RED1[3].y)) * fac1;
            #pragma unroll
            for (int j = 0; j < 4; j++) {
                y[j].x -= d.x*v1v[j].x - d.y*v1v[j].y;
                y[j].y -= d.x*v1v[j].y + d.y*v1v[j].x;
            }
        }

        // ph3: publish owned -> gather permuted canonical, *e2
        #pragma unroll
        for (int j = 0; j < 4; j++) SB[oaddr[j]] = y[j];
        __syncthreads();                                              // 3
        #pragma unroll
        for (int r = 0; r < 4; r++) y[r] = cmul(SB[paddr[r]], e2r[r]);

        // ph4: inverse FFT-512
        dft4<1>(y[0], y[1], y[2], y[3]);
        y[1] = cmulc(y[1], c512[0]);
        y[2] = cmulc(y[2], c512[1]);
        y[3] = cmulc(y[3], c512[2]);
        #pragma unroll
        for (int r = 0; r < 4; r++) SA[r*128 + tid] = y[r];
        __syncthreads();                                              // 4
        #pragma unroll
        for (int q = 0; q < 4; q++) y[q] = SA[w*128 + 32*q + lane];
        dft4<1>(y[0], y[1], y[2], y[3]);
        y[1] = cmulc(y[1], d128[0]);
        y[2] = cmulc(y[2], d128[1]);
        y[3] = cmulc(y[3], d128[2]);
        fft32<1>(y, tw32c, lane);                 // owned order

        // ph5: dot2 + reflect2 in owned space
        float2 v2v[4];
        {
            float dx = 0.f, dy = 0.f;
            #pragma unroll
            for (int j = 0; j < 4; j++) {
                v2v[j] = V2o[oaddr[j]];
                dx += y[j].x*v2v[j].x + y[j].y*v2v[j].y;
                dy += y[j].y*v2v[j].x - y[j].x*v2v[j].y;
            }
            #pragma unroll
            for (int off = 16; off; off >>= 1) {
                dx += __shfl_xor_sync(0xffffffffu, dx, off);
                dy += __shfl_xor_sync(0xffffffffu, dy, off);
            }
            if (lane == 0) RED2[w] = make_float2(dx, dy);
        }
        __syncthreads();                                              // 5
        {
            float2 d;
            d.x = ((RED2[0].x + RED2[1].x) + (RED2[2].x + RED2[3].x)) * fac2;
            d.y = ((RED2[0].y + RED2[1].y) + (RED2[2].y + RED2[3].y)) * fac2;
            #pragma unroll
            for (int j = 0; j < 4; j++) {
                y[j].x -= d.x*v2v[j].x - d.y*v2v[j].y;
                y[j].y -= d.x*v2v[j].y + d.y*v2v[j].x;
            }
        }

        // ph6: restore canonical + epilogue
        #pragma unroll
        for (int j = 0; j < 4; j++) SB[oaddr[j]] = y[j];
        __syncthreads();                                              // 6
        const int orow = (brow + t) * (2*H_);
        #pragma unroll
        for (int r = 0; r < 4; r++) {
            int ra = ((tid >> 4) + 8*r)*17 + (tid & 15);
            float2 s = cmul(SB[ra], e3r[r]);          // e3 pre-scaled 1/512
            float2 pre = make_float2(u0[r].x + s.x, u0[r].y + s.y);
            float norm = sqrtf(pre.x*pre.x + pre.y*pre.y);
            float sc = fmaxf(norm + bhr[r], 0.f) / (norm + 1e-6f);
            float2 nw = make_float2(pre.x*sc, pre.y*sc);
            h[r] = nw;
            int idx = tid + 128*r;
            __nv_bfloat16 hx = __float2bfloat16(nw.x);
            __nv_bfloat16 hy = __float2bfloat16(nw.y);
            g_outsH[orow + idx]       = hx;
            g_outsL[orow + idx]       = __float2bfloat16(nw.x - __bfloat162float(hx));
            g_outsH[orow + 512 + idx] = hy;
            g_outsL[orow + 512 + idx] = __float2bfloat16(nw.y - __bfloat162float(hy));
        }
    }

    #pragma unroll
    for (int r = 0; r < 4; r++) {
        int idx = tid + 128*r;
        dout[OUT_OFF + b*1024 + idx]       = h[r].x;
        dout[OUT_OFF + b*1024 + 512 + idx] = h[r].y;
    }
}

// =========================================================================
// bf16x3 GEMM: pre-split operands, cp.async double buffer, ldmatrix frags
// =========================================================================
#define MMA16816(d, a, b)                                                     \
    asm volatile("mma.sync.aligned.m16n8k16.row.col.f32.bf16.bf16.f32 "       \
                 "{%0,%1,%2,%3}, {%4,%5,%6,%7}, {%8,%9}, {%0,%1,%2,%3};\n"    \
                 : "+f"(d[0]), "+f"(d[1]), "+f"(d[2]), "+f"(d[3])             \
                 : "r"(a[0]), "r"(a[1]), "r"(a[2]), "r"(a[3]),                \
                   "r"(b[0]), "r"(b[1]))

#define LDMX4(r0, r1, r2, r3, addr)                                           \
    asm volatile("ldmatrix.sync.aligned.m8n8.x4.shared.b16 {%0,%1,%2,%3}, [%4];" \
                 : "=r"(r0), "=r"(r1), "=r"(r2), "=r"(r3) : "r"(addr))

__device__ __forceinline__ void cp16(void* dst, const void* src) {
    uint32_t d = (uint32_t)__cvta_generic_to_shared(dst);
    asm volatile("cp.async.cg.shared.global [%0], [%1], 16;\n" :: "r"(d), "l"(src));
}

#define AS(p, buf, hl, r, c) (p)[((((buf)*2 + (hl))*128 + (r))*40) + (c)]
#define BS(p, buf, hl, r, c) (p)[((((buf)*2 + (hl))*64  + (r))*40) + (c)]
#define GEMM_SMEM ((2*2*128*40 + 2*2*64*40) * 2)

template<int MODE>
__global__ __launch_bounds__(256)
void gemm_bf16s(const float* __restrict__ bias,
                float* __restrict__ C, int M, int N, int K)
{
    extern __shared__ __nv_bfloat16 smem[];
    __nv_bfloat16* Asm = smem;
    __nv_bfloat16* Bsm = smem + 2*2*128*40;

    const __nv_bfloat16* AH = (MODE == 0) ? g_xH : g_outsH;
    const __nv_bfloat16* AL = (MODE == 0) ? g_xL : g_outsL;
    const __nv_bfloat16* WH = (MODE == 0) ? g_w1H : g_w2H;
    const __nv_bfloat16* WL = (MODE == 0) ? g_w1L : g_w2L;

    const int tid = threadIdx.x;
    const int wid = tid >> 5, lane = tid & 31;
    const int wm = wid >> 1, wn = wid & 1;
    const int groupID = lane >> 2, tig = lane & 3;
    const int bm0 = blockIdx.y * 128;
    const int bn0 = blockIdx.x * 64;
    const int KT = K / 32;

    const int ar0 = tid >> 2,         aq0 = (tid & 3) * 8;
    const int ar1 = (tid + 256) >> 2, aq1 = aq0;
    const int br  = tid >> 2,         bq  = (tid & 3) * 8;

    const int a_row = (lane & 15);
    const int a_col = (lane >> 4) * 8;
    const int b_row = ((lane >> 4) << 3) + (lane & 7);
    const int b_col = ((lane >> 3) & 1) * 8;

    float acc[2][4][4];
    #pragma unroll
    for (int mi = 0; mi < 2; mi++)
        #pragma unroll
        for (int ni = 0; ni < 4; ni++)
            #pragma unroll
            for (int j = 0; j < 4; j++) acc[mi][ni][j] = 0.f;

    auto load_tile = [&](int kt, int buf) {
        int k0 = kt * 32;
        cp16(&AS(Asm, buf, 0, ar0, aq0), AH + (size_t)(bm0 + ar0)*K + k0 + aq0);
        cp16(&AS(Asm, buf, 0, ar1, aq1), AH + (size_t)(bm0 + ar1)*K + k0 + aq1);
        cp16(&AS(Asm, buf, 1, ar0, aq0), AL + (size_t)(bm0 + ar0)*K + k0 + aq0);
        cp16(&AS(Asm, buf, 1, ar1, aq1), AL + (size_t)(bm0 + ar1)*K + k0 + aq1);
        cp16(&BS(Bsm, buf, 0, br, bq),   WH + (size_t)(bn0 + br)*K + k0 + bq);
        cp16(&BS(Bsm, buf, 1, br, bq),   WL + (size_t)(bn0 + br)*K + k0 + bq);
    };

    load_tile(0, 0);
    asm volatile("cp.async.commit_group;\n");

    for (int kt = 0; kt < KT; kt++) {
        const int buf = kt & 1;
        if (kt + 1 < KT) {
            load_tile(kt + 1, (kt + 1) & 1);
            asm volatile("cp.async.commit_group;\n");
            asm volatile("cp.async.wait_group 1;\n");
        } else {
            asm volatile("cp.async.wait_group 0;\n");
        }
        __syncthreads();

        #pragma unroll
        for (int kk = 0; kk < 2; kk++) {
            const int kb = kk * 16;
            uint32_t aH[2][4], aL[2][4], bH[4][2], bL[4][2];
            #pragma unroll
            for (int mi = 0; mi < 2; mi++) {
                uint32_t adrH = (uint32_t)__cvta_generic_to_shared(
                    &AS(Asm, buf, 0, wm*32 + mi*16 + a_row, kb + a_col));
                uint32_t adrL = (uint32_t)__cvta_generic_to_shared(
                    &AS(Asm, buf, 1, wm*32 + mi*16 + a_row, kb + a_col));
                LDMX4(aH[mi][0], aH[mi][1], aH[mi][2], aH[mi][3], adrH);
                LDMX4(aL[mi][0], aL[mi][1], aL[mi][2], aL[mi][3], adrL);
            }
            #pragma unroll
            for (int nip = 0; nip < 2; nip++) {
                uint32_t adrH = (uint32_t)__cvta_generic_to_shared(
                    &BS(Bsm, buf, 0, wn*32 + nip*16 + b_row, kb + b_col));
                uint32_t adrL = (uint32_t)__cvta_generic_to_shared(
                    &BS(Bsm, buf, 1, wn*32 + nip*16 + b_row, kb + b_col));
                LDMX4(bH[2*nip][0], bH[2*nip][1], bH[2*nip+1][0], bH[2*nip+1][1], adrH);
                LDMX4(bL[2*nip][0], bL[2*nip][1], bL[2*nip+1][0], bL[2*nip+1][1], adrL);
            }
            #pragma unroll
            for (int mi = 0; mi < 2; mi++)
                #pragma unroll
                for (int ni = 0; ni < 4; ni++) {
                    MMA16816(acc[mi][ni], aH[mi], bH[ni]);
                    MMA16816(acc[mi][ni], aH[mi], bL[ni]);
                    MMA16816(acc[mi][ni], aL[mi], bH[ni]);
                }
        }
        __syncthreads();
    }

    #pragma unroll
    for (int mi = 0; mi < 2; mi++) {
        #pragma unroll
        for (int ni = 0; ni < 4; ni++) {
            int r0 = bm0 + wm*32 + mi*16 + groupID;
            int c0 = bn0 + wn*32 + ni*8 + 2*tig;
            float v00 = acc[mi][ni][0], v01 = acc[mi][ni][1];
            float v10 = acc[mi][ni][2], v11 = acc[mi][ni][3];
            if (MODE == 0) {
                #pragma unroll
                for (int q = 0; q < 4; q++) {
                    int rr = (q < 2) ? r0 : (r0 + 8);
                    int cc = (q & 1) ? (c0 + 1) : c0;
                    float vv = (q==0)?v00:(q==1)?v01:(q==2)?v10:v11;
                    if (cc < 512) g_u[(size_t)rr*512 + cc].x = vv;
                    else          g_u[(size_t)rr*512 + cc - 512].y = vv;
                }
            } else {
                float b0 = bias[c0], b1 = bias[c0 + 1];
                C[(size_t)r0*N + c0]         = v00 + b0;
                C[(size_t)r0*N + c0 + 1]     = v01 + b1;
                C[(size_t)(r0+8)*N + c0]     = v10 + b0;
                C[(size_t)(r0+8)*N + c0 + 1] = v11 + b1;
            }
        }
    }
}

extern "C" void kernel_launch(void* const* d_in, const int* in_sizes, int n_in,
                              void* d_out, int out_size)
{
    const float* x    = (const float*)d_in[0];
    const float* h0   = (const float*)d_in[1];
    const float* itoh = (const float*)d_in[2];
    const float* fcw  = (const float*)d_in[3];
    const float* fcb  = (const float*)d_in[4];
    const float* bh   = (const float*)d_in[5];
    const float* d1   = (const float*)d_in[6];
    const float* d2   = (const float*)d_in[7];
    const float* d3   = (const float*)d_in[8];
    const float* r1re = (const float*)d_in[9];
    const float* r1im = (const float*)d_in[10];
    const float* r2re = (const float*)d_in[11];
    const float* r2im = (const float*)d_in[12];
    const int*   perm = (const int*)d_in[13];
    float* out = (float*)d_out;

    cudaFuncSetAttribute(gemm_bf16s<0>, cudaFuncAttributeMaxDynamicSharedMemorySize, GEMM_SMEM);
    cudaFuncSetAttribute(gemm_bf16s<1>, cudaFuncAttributeMaxDynamicSharedMemorySize, GEMM_SMEM);

    {
        int n4 = (MROWS*IN_) / 4;
        split_kernel<0><<<(n4 + 255)/256, 256>>>(x, n4);
        n4 = (2*H_*IN_) / 4;
        split_kernel<1><<<(n4 + 255)/256, 256>>>(itoh, n4);
        n4 = (OUT_*2*H_) / 4;
        split_kernel<2><<<(n4 + 255)/256, 256>>>(fcw, n4);
    }

    gemm_bf16s<0><<<dim3(1024/64, MROWS/128), 256, GEMM_SMEM>>>(nullptr, nullptr,
                                                                MROWS, 1024, 256);
    scan_kernel<<<B_, 128>>>(h0, bh, d1, d2, d3, r1re, r1im, r2re, r2im, perm, out);
    gemm_bf16s<1><<<dim3(256/64, MROWS/128), 256, GEMM_SMEM>>>(fcb, out,
                                                               MROWS, 256, 1024);
}

// round 7
// speedup vs baseline: 1.7433x; 1.2194x over previous
#include <cuda_runtime.h>
#include <cuda_bf16.h>
#include <cstdint>

#define B_   64
#define T_   512
#define IN_  256
#define OUT_ 256
#define H_   512
#define MROWS (B_*T_)
#define OUT_OFF (B_*T_*OUT_)

__device__ __align__(16) float2 g_u[MROWS*H_];
__device__ __align__(16) __nv_bfloat16 g_outsH[MROWS*2*H_];
__device__ __align__(16) __nv_bfloat16 g_outsL[MROWS*2*H_];
__device__ __align__(16) __nv_bfloat16 g_xH[MROWS*IN_];
__device__ __align__(16) __nv_bfloat16 g_xL[MROWS*IN_];
__device__ __align__(16) __nv_bfloat16 g_w1H[2*H_*IN_];
__device__ __align__(16) __nv_bfloat16 g_w1L[2*H_*IN_];
__device__ __align__(16) __nv_bfloat16 g_w2H[OUT_*2*H_];
__device__ __align__(16) __nv_bfloat16 g_w2L[OUT_*2*H_];

__device__ __forceinline__ float2 cadd(float2 a, float2 b){return make_float2(a.x+b.x, a.y+b.y);}
__device__ __forceinline__ float2 csub(float2 a, float2 b){return make_float2(a.x-b.x, a.y-b.y);}
__device__ __forceinline__ float2 cmul(float2 a, float2 b){return make_float2(a.x*b.x-a.y*b.y, a.x*b.y+a.y*b.x);}
__device__ __forceinline__ float2 cmulc(float2 a, float2 b){return make_float2(a.x*b.x+a.y*b.y, a.y*b.x-a.x*b.y);}
__device__ __forceinline__ float2 mulpi(float2 a){return make_float2(-a.y, a.x);}
__device__ __forceinline__ float2 mulmi(float2 a){return make_float2(a.y, -a.x);}

template<int WHICH>
__global__ void split_kernel(const float* __restrict__ src, int n4)
{
    __nv_bfloat16 *hi, *lo;
    if (WHICH == 0) { hi = g_xH;  lo = g_xL;  }
    if (WHICH == 1) { hi = g_w1H; lo = g_w1L; }
    if (WHICH == 2) { hi = g_w2H; lo = g_w2L; }
    int i = blockIdx.x * blockDim.x + threadIdx.x;
    if (i >= n4) return;
    float4 v = ((const float4*)src)[i];
    const float* pv = (const float*)&v;
    #pragma unroll
    for (int j = 0; j < 4; j++) {
        __nv_bfloat16 h = __float2bfloat16(pv[j]);
        hi[4*i + j] = h;
        lo[4*i + j] = __float2bfloat16(pv[j] - __bfloat162float(h));
    }
}

template<int INV>
__device__ __forceinline__ void dft4(float2& x0, float2& x1, float2& x2, float2& x3)
{
    float2 t0 = cadd(x0, x2), t2 = csub(x0, x2);
    float2 t1 = cadd(x1, x3), t3 = csub(x1, x3);
    float2 a1 = INV ? mulpi(t3) : mulmi(t3);
    float2 a3 = INV ? mulmi(t3) : mulpi(t3);
    x0 = cadd(t0, t1);
    x1 = cadd(t2, a1);
    x2 = csub(t0, t1);
    x3 = cadd(t2, a3);
}

// DIF radix-2 FFT-32 across lanes on 4 regs; output at lane l = comp rev5(l).
template<int INV>
__device__ __forceinline__ void fft32(float2 y[4], const float2 tw32[5], int lane)
{
    #pragma unroll
    for (int s = 0; s < 5; s++) {
        const int st = 16 >> s;
        const bool hi = (lane & st) != 0;
        const float2 tw = tw32[s];
        #pragma unroll
        for (int j = 0; j < 4; j++) {
            float2 v = y[j], pv;
            pv.x = __shfl_xor_sync(0xffffffffu, v.x, st);
            pv.y = __shfl_xor_sync(0xffffffffu, v.y, st);
            float2 sum = cadd(v, pv);
            float2 dif = csub(pv, v);
            float2 tv  = INV ? cmulc(dif, tw) : cmul(dif, tw);
            y[j] = hi ? tv : sum;
        }
    }
}

// =========================================================================
// Scan: 1 chain/CTA, 128 thr, hybrid FFT (4 regs x 4 regs x 32 lanes).
// Reflections pulled off the critical path via linearity:
//   y = y0 - c1*W,  W = IFFT(P(v1).e2) precomputed
//   c2 = fac2<y0,v2> - c1*K,  K = fac2<W,v2> precomputed
//   s = y0.e3' - c1*(W.e3') - c2*(v2.e3')
// 4 __syncthreads per step; dot1 fully hidden under IFFT.
// =========================================================================
__global__ __launch_bounds__(128)
void scan_kernel(const float* __restrict__ h0,
                 const float* __restrict__ b_h,
                 const float* __restrict__ d1,
                 const float* __restrict__ d2,
                 const float* __restrict__ d3,
                 const float* __restrict__ r1re, const float* __restrict__ r1im,
                 const float* __restrict__ r2re, const float* __restrict__ r2im,
                 const int*   __restrict__ perm,
                 float* __restrict__ dout)
{
    __shared__ float2 SA[544], SB[544];
    __shared__ float2 WE3[544], V2E3[544];
    __shared__ float2 RED1[4], RED2[4];
    __shared__ float  FAC[2];

    const int b    = blockIdx.x;
    const int tid  = threadIdx.x;
    const int lane = tid & 31;
    const int w    = tid >> 5;
    const int R    = __brev(lane) >> 27;      // rev5(lane)

    int oaddr[4];
    #pragma unroll
    for (int j = 0; j < 4; j++) oaddr[j] = R*17 + w + 4*j;

    float2 h[4], e1r[4], e2r[4], e3r[4], v1o[4], v2o[4];
    float bhr[4]; int paddr[4], caddr[4];
    const float inv512 = 1.0f / 512.0f;
    #pragma unroll
    for (int r = 0; r < 4; r++) {
        int idx = tid + 128*r;
        float sn, cs;
        sincosf(d1[idx], &sn, &cs); e1r[r] = make_float2(cs, sn);
        sincosf(d2[idx], &sn, &cs); e2r[r] = make_float2(cs, sn);
        sincosf(d3[idx], &sn, &cs); e3r[r] = make_float2(cs*inv512, sn*inv512);
        bhr[r] = b_h[idx];
        int p = perm[idx];
        paddr[r] = (p >> 4)*17 + (p & 15);
        caddr[r] = (idx >> 4)*17 + (idx & 15);
        h[r] = make_float2(h0[b*1024 + idx], h0[b*1024 + 512 + idx]);
    }
    // owned-space v1, v2 (registers; owned index = w + 4j + 16*R)
    #pragma unroll
    for (int j = 0; j < 4; j++) {
        int oi = w + 4*j + 16*R;
        v1o[j] = make_float2(r1re[oi], r1im[oi]);
        v2o[j] = make_float2(r2re[oi], r2im[oi]);
    }

    const float TWO_PI = 6.283185307179586f;
    float2 c512[3], d128[3], tw32c[5];
    #pragma unroll
    for (int k = 1; k <= 3; k++) {
        float sn, cs;
        sincosf(-TWO_PI * (float)(tid*k) / 512.0f, &sn, &cs);
        c512[k-1] = make_float2(cs, sn);
        sincosf(-TWO_PI * (float)(lane*k) / 128.0f, &sn, &cs);
        d128[k-1] = make_float2(cs, sn);
    }
    #pragma unroll
    for (int s = 0; s < 5; s++) {
        int st = 16 >> s;
        int e  = (lane & (st - 1)) << s;
        float sn, cs;
        sincosf(-TWO_PI * (float)e / 32.0f, &sn, &cs);
        tw32c[s] = make_float2(cs, sn);
    }

    // ---- fac1/fac2 ----
    {
        float n1 = 0.f, n2 = 0.f;
        #pragma unroll
        for (int r = 0; r < 4; r++) {
            int idx = tid + 128*r;
            n1 += r1re[idx]*r1re[idx] + r1im[idx]*r1im[idx];
            n2 += r2re[idx]*r2re[idx] + r2im[idx]*r2im[idx];
        }
        #pragma unroll
        for (int off = 16; off; off >>= 1) {
            n1 += __shfl_xor_sync(0xffffffffu, n1, off);
            n2 += __shfl_xor_sync(0xffffffffu, n2, off);
        }
        if (lane == 0) RED1[w] = make_float2(n1, n2);
        __syncthreads();
        if (tid == 0) {
            float a  = (RED1[0].x + RED1[1].x) + (RED1[2].x + RED1[3].x);
            float bb = (RED1[0].y + RED1[1].y) + (RED1[2].y + RED1[3].y);
            FAC[0] = 2.f / a; FAC[1] = 2.f / bb;
        }
        __syncthreads();
    }
    const float fac1 = FAC[0], fac2 = FAC[1];

    // ---- precompute W = IFFT(P(v1).e2), K = fac2<W,v2>, tables WE3/V2E3 ----
    float Kx, Ky;
    {
        for (int i = tid; i < 512; i += 128) {
            int a = (i >> 4)*17 + (i & 15);
            SB[a] = make_float2(r1re[i], r1im[i]);     // v1 canonical
        }
        __syncthreads();
        float2 yw[4];
        #pragma unroll
        for (int r = 0; r < 4; r++) yw[r] = cmul(SB[paddr[r]], e2r[r]);
        dft4<1>(yw[0], yw[1], yw[2], yw[3]);
        yw[1] = cmulc(yw[1], c512[0]);
        yw[2] = cmulc(yw[2], c512[1]);
        yw[3] = cmulc(yw[3], c512[2]);
        #pragma unroll
        for (int r = 0; r < 4; r++) SA[r*128 + tid] = yw[r];
        __syncthreads();
        #pragma unroll
        for (int q = 0; q < 4; q++) yw[q] = SA[w*128 + 32*q + lane];
        dft4<1>(yw[0], yw[1], yw[2], yw[3]);
        yw[1] = cmulc(yw[1], d128[0]);
        yw[2] = cmulc(yw[2], d128[1]);
        yw[3] = cmulc(yw[3], d128[2]);
        fft32<1>(yw, tw32c, lane);                     // W owned

        // K partials
        float dx = 0.f, dy = 0.f;
        #pragma unroll
        for (int j = 0; j < 4; j++) {
            dx += yw[j].x*v2o[j].x + yw[j].y*v2o[j].y;
            dy += yw[j].y*v2o[j].x - yw[j].x*v2o[j].y;
        }
        #pragma unroll
        for (int off = 16; off; off >>= 1) {
            dx += __shfl_xor_sync(0xffffffffu, dx, off);
            dy += __shfl_xor_sync(0xffffffffu, dy, off);
        }
        if (lane == 0) RED2[w] = make_float2(dx, dy);
        // publish W owned -> canonical (SB reads above all done pre-transpose-sync)
        #pragma unroll
        for (int j = 0; j < 4; j++) SB[oaddr[j]] = yw[j];
        __syncthreads();
        Kx = ((RED2[0].x + RED2[1].x) + (RED2[2].x + RED2[3].x)) * fac2;
        Ky = ((RED2[0].y + RED2[1].y) + (RED2[2].y + RED2[3].y)) * fac2;
        for (int i = tid; i < 512; i += 128) {
            int a = (i >> 4)*17 + (i & 15);
            float sn, cs; sincosf(d3[i], &sn, &cs);
            float2 e3i = make_float2(cs*inv512, sn*inv512);
            WE3[a]  = cmul(SB[a], e3i);
            V2E3[a] = cmul(make_float2(r2re[i], r2im[i]), e3i);
        }
        __syncthreads();
    }

    const int brow = b * T_;

    for (int t = 0; t < T_; t++) {
        float2 u0[4];
        {
            const float2* up = g_u + (size_t)(brow + t) * H_;
            #pragma unroll
            for (int r = 0; r < 4; r++) u0[r] = up[tid + 128*r];
        }

        // ph1: fwd FFT part 1
        float2 y[4];
        #pragma unroll
        for (int r = 0; r < 4; r++) y[r] = cmul(h[r], e1r[r]);
        dft4<0>(y[0], y[1], y[2], y[3]);
        y[1] = cmul(y[1], c512[0]);
        y[2] = cmul(y[2], c512[1]);
        y[3] = cmul(y[3], c512[2]);
        #pragma unroll
        for (int r = 0; r < 4; r++) SA[r*128 + tid] = y[r];
        __syncthreads();                                              // S1

        // ph2: fwd FFT part 2 -> z owned; publish z + dot1 partials
        #pragma unroll
        for (int q = 0; q < 4; q++) y[q] = SA[w*128 + 32*q + lane];
        dft4<0>(y[0], y[1], y[2], y[3]);
        y[1] = cmul(y[1], d128[0]);
        y[2] = cmul(y[2], d128[1]);
        y[3] = cmul(y[3], d128[2]);
        fft32<0>(y, tw32c, lane);
        #pragma unroll
        for (int j = 0; j < 4; j++) SB[oaddr[j]] = y[j];
        {
            float dx = 0.f, dy = 0.f;
            #pragma unroll
            for (int j = 0; j < 4; j++) {
                dx += y[j].x*v1o[j].x + y[j].y*v1o[j].y;
                dy += y[j].y*v1o[j].x - y[j].x*v1o[j].y;
            }
            #pragma unroll
            for (int off = 16; off; off >>= 1) {
                dx += __shfl_xor_sync(0xffffffffu, dx, off);
                dy += __shfl_xor_sync(0xffffffffu, dy, off);
            }
            if (lane == 0) RED1[w] = make_float2(dx, dy);
        }
        __syncthreads();                                              // S2

        // ph3: gather permuted z (unreflected) * e2; IFFT part 1
        #pragma unroll
        for (int r = 0; r < 4; r++) y[r] = cmul(SB[paddr[r]], e2r[r]);
        dft4<1>(y[0], y[1], y[2], y[3]);
        y[1] = cmulc(y[1], c512[0]);
        y[2] = cmulc(y[2], c512[1]);
        y[3] = cmulc(y[3], c512[2]);
        #pragma unroll
        for (int r = 0; r < 4; r++) SA[r*128 + tid] = y[r];
        __syncthreads();                                              // S3

        // ph4: IFFT part 2 -> y0 owned; dot2 partials; publish y0
        #pragma unroll
        for (int q = 0; q < 4; q++) y[q] = SA[w*128 + 32*q + lane];
        dft4<1>(y[0], y[1], y[2], y[3]);
        y[1] = cmulc(y[1], d128[0]);
        y[2] = cmulc(y[2], d128[1]);
        y[3] = cmulc(y[3], d128[2]);
        fft32<1>(y, tw32c, lane);
        #pragma unroll
        for (int j = 0; j < 4; j++) SB[oaddr[j]] = y[j];
        {
            float dx = 0.f, dy = 0.f;
            #pragma unroll
            for (int j = 0; j < 4; j++) {
                dx += y[j].x*v2o[j].x + y[j].y*v2o[j].y;
                dy += y[j].y*v2o[j].x - y[j].x*v2o[j].y;
            }
            #pragma unroll
            for (int off = 16; off; off >>= 1) {
                dx += __shfl_xor_sync(0xffffffffu, dx, off);
                dy += __shfl_xor_sync(0xffffffffu, dy, off);
            }
            if (lane == 0) RED2[w] = make_float2(dx, dy);
        }
        __syncthreads();                                              // S4

        // ph5: epilogue (canonical)
        float2 c1, c2;
        c1.x = ((RED1[0].x + RED1[1].x) + (RED1[2].x + RED1[3].x)) * fac1;
        c1.y = ((RED1[0].y + RED1[1].y) + (RED1[2].y + RED1[3].y)) * fac1;
        float d2x = (RED2[0].x + RED2[1].x) + (RED2[2].x + RED2[3].x);
        float d2y = (RED2[0].y + RED2[1].y) + (RED2[2].y + RED2[3].y);
        // c2 = fac2*<y0,v2> - c1*K   (complex)
        c2.x = fac2*d2x - (c1.x*Kx - c1.y*Ky);
        c2.y = fac2*d2y - (c1.x*Ky + c1.y*Kx);

        const int orow = (brow + t) * (2*H_);
        #pragma unroll
        for (int r = 0; r < 4; r++) {
            int a = caddr[r];
            float2 y0c = SB[a];
            float2 s = cmul(y0c, e3r[r]);
            float2 we = WE3[a], ve = V2E3[a];
            s.x -= c1.x*we.x - c1.y*we.y;
            s.y -= c1.x*we.y + c1.y*we.x;
            s.x -= c2.x*ve.x - c2.y*ve.y;
            s.y -= c2.x*ve.y + c2.y*ve.x;
            float2 pre = make_float2(u0[r].x + s.x, u0[r].y + s.y);
            float norm = sqrtf(pre.x*pre.x + pre.y*pre.y);
            float sc = fmaxf(norm + bhr[r], 0.f) / (norm + 1e-6f);
            float2 nw = make_float2(pre.x*sc, pre.y*sc);
            h[r] = nw;
            int idx = tid + 128*r;
            __nv_bfloat16 hx = __float2bfloat16(nw.x);
            __nv_bfloat16 hy = __float2bfloat16(nw.y);
            g_outsH[orow + idx]       = hx;
            g_outsL[orow + idx]       = __float2bfloat16(nw.x - __bfloat162float(hx));
            g_outsH[orow + 512 + idx] = hy;
            g_outsL[orow + 512 + idx] = __float2bfloat16(nw.y - __bfloat162float(hy));
        }
        // safety: SA rewritten only after next S1-preceding code (ph1 STS) which
        // all threads reach after finishing ph5 (S1 is the separating barrier of
        // the next iteration via S4->ph5->ph1 order within each thread, and SB/RED
        // rewrites happen after next S1/S2 respectively).
    }

    #pragma unroll
    for (int r = 0; r < 4; r++) {
        int idx = tid + 128*r;
        dout[OUT_OFF + b*1024 + idx]       = h[r].x;
        dout[OUT_OFF + b*1024 + 512 + idx] = h[r].y;
    }
}

// =========================================================================
// bf16x3 GEMM: pre-split operands, cp.async double buffer, ldmatrix frags
// =========================================================================
#define MMA16816(d, a, b)                                                     \
    asm volatile("mma.sync.aligned.m16n8k16.row.col.f32.bf16.bf16.f32 "       \
                 "{%0,%1,%2,%3}, {%4,%5,%6,%7}, {%8,%9}, {%0,%1,%2,%3};\n"    \
                 : "+f"(d[0]), "+f"(d[1]), "+f"(d[2]), "+f"(d[3])             \
                 : "r"(a[0]), "r"(a[1]), "r"(a[2]), "r"(a[3]),                \
                   "r"(b[0]), "r"(b[1]))

#define LDMX4(r0, r1, r2, r3, addr)                                           \
    asm volatile("ldmatrix.sync.aligned.m8n8.x4.shared.b16 {%0,%1,%2,%3}, [%4];" \
                 : "=r"(r0), "=r"(r1), "=r"(r2), "=r"(r3) : "r"(addr))

__device__ __forceinline__ void cp16(void* dst, const void* src) {
    uint32_t d = (uint32_t)__cvta_generic_to_shared(dst);
    asm volatile("cp.async.cg.shared.global [%0], [%1], 16;\n" :: "r"(d), "l"(src));
}

#define AS(p, buf, hl, r, c) (p)[((((buf)*2 + (hl))*128 + (r))*40) + (c)]
#define BS(p, buf, hl, r, c) (p)[((((buf)*2 + (hl))*64  + (r))*40) + (c)]
#define GEMM_SMEM ((2*2*128*40 + 2*2*64*40) * 2)

template<int MODE>
__global__ __launch_bounds__(256)
void gemm_bf16s(const float* __restrict__ bias,
                float* __restrict__ C, int M, int N, int K)
{
    extern __shared__ __nv_bfloat16 smem[];
    __nv_bfloat16* Asm = smem;
    __nv_bfloat16* Bsm = smem + 2*2*128*40;

    const __nv_bfloat16* AH = (MODE == 0) ? g_xH : g_outsH;
    const __nv_bfloat16* AL = (MODE == 0) ? g_xL : g_outsL;
    const __nv_bfloat16* WH = (MODE == 0) ? g_w1H : g_w2H;
    const __nv_bfloat16* WL = (MODE == 0) ? g_w1L : g_w2L;

    const int tid = threadIdx.x;
    const int wid = tid >> 5, lane = tid & 31;
    const int wm = wid >> 1, wn = wid & 1;
    const int groupID = lane >> 2, tig = lane & 3;
    const int bm0 = blockIdx.y * 128;
    const int bn0 = blockIdx.x * 64;
    const int KT = K / 32;

    const int ar0 = tid >> 2,         aq0 = (tid & 3) * 8;
    const int ar1 = (tid + 256) >> 2, aq1 = aq0;
    const int br  = tid >> 2,         bq  = (tid & 3) * 8;

    const int a_row = (lane & 15);
    const int a_col = (lane >> 4) * 8;
    const int b_row = ((lane >> 4) << 3) + (lane & 7);
    const int b_col = ((lane >> 3) & 1) * 8;

    float acc[2][4][4];
    #pragma unroll
    for (int mi = 0; mi < 2; mi++)
        #pragma unroll
        for (int ni = 0; ni < 4; ni++)
            #pragma unroll
            for (int j = 0; j < 4; j++) acc[mi][ni][j] = 0.f;

    auto load_tile = [&](int kt, int buf) {
        int k0 = kt * 32;
        cp16(&AS(Asm, buf, 0, ar0, aq0), AH + (size_t)(bm0 + ar0)*K + k0 + aq0);
        cp16(&AS(Asm, buf, 0, ar1, aq1), AH + (size_t)(bm0 + ar1)*K + k0 + aq1);
        cp16(&AS(Asm, buf, 1, ar0, aq0), AL + (size_t)(bm0 + ar0)*K + k0 + aq0);
        cp16(&AS(Asm, buf, 1, ar1, aq1), AL + (size_t)(bm0 + ar1)*K + k0 + aq1);
        cp16(&BS(Bsm, buf, 0, br, bq),   WH + (size_t)(bn0 + br)*K + k0 + bq);
        cp16(&BS(Bsm, buf, 1, br, bq),   WL + (size_t)(bn0 + br)*K + k0 + bq);
    };

    load_tile(0, 0);
    asm volatile("cp.async.commit_group;\n");

    for (int kt = 0; kt < KT; kt++) {
        const int buf = kt & 1;
        if (kt + 1 < KT) {
            load_tile(kt + 1, (kt + 1) & 1);
            asm volatile("cp.async.commit_group;\n");
            asm volatile("cp.async.wait_group 1;\n");
        } else {
            asm volatile("cp.async.wait_group 0;\n");
        }
        __syncthreads();

        #pragma unroll
        for (int kk = 0; kk < 2; kk++) {
            const int kb = kk * 16;
            uint32_t aH[2][4], aL[2][4], bH[4][2], bL[4][2];
            #pragma unroll
            for (int mi = 0; mi < 2; mi++) {
                uint32_t adrH = (uint32_t)__cvta_generic_to_shared(
                    &AS(Asm, buf, 0, wm*32 + mi*16 + a_row, kb + a_col));
                uint32_t adrL = (uint32_t)__cvta_generic_to_shared(
                    &AS(Asm, buf, 1, wm*32 + mi*16 + a_row, kb + a_col));
                LDMX4(aH[mi][0], aH[mi][1], aH[mi][2], aH[mi][3], adrH);
                LDMX4(aL[mi][0], aL[mi][1], aL[mi][2], aL[mi][3], adrL);
            }
            #pragma unroll
            for (int nip = 0; nip < 2; nip++) {
                uint32_t adrH = (uint32_t)__cvta_generic_to_shared(
                    &BS(Bsm, buf, 0, wn*32 + nip*16 + b_row, kb + b_col));
                uint32_t adrL = (uint32_t)__cvta_generic_to_shared(
                    &BS(Bsm, buf, 1, wn*32 + nip*16 + b_row, kb + b_col));
                LDMX4(bH[2*nip][0], bH[2*nip][1], bH[2*nip+1][0], bH[2*nip+1][1], adrH);
                LDMX4(bL[2*nip][0], bL[2*nip][1], bL[2*nip+1][0], bL[2*nip+1][1], adrL);
            }
            #pragma unroll
            for (int mi = 0; mi < 2; mi++)
                #pragma unroll
                for (int ni = 0; ni < 4; ni++) {
                    MMA16816(acc[mi][ni], aH[mi], bH[ni]);
                    MMA16816(acc[mi][ni], aH[mi], bL[ni]);
                    MMA16816(acc[mi][ni], aL[mi], bH[ni]);
                }
        }
        __syncthreads();
    }

    #pragma unroll
    for (int mi = 0; mi < 2; mi++) {
        #pragma unroll
        for (int ni = 0; ni < 4; ni++) {
            int r0 = bm0 + wm*32 + mi*16 + groupID;
            int c0 = bn0 + wn*32 + ni*8 + 2*tig;
            float v00 = acc[mi][ni][0], v01 = acc[mi][ni][1];
            float v10 = acc[mi][ni][2], v11 = acc[mi][ni][3];
            if (MODE == 0) {
                #pragma unroll
                for (int q = 0; q < 4; q++) {
                    int rr = (q < 2) ? r0 : (r0 + 8);
                    int cc = (q & 1) ? (c0 + 1) : c0;
                    float vv = (q==0)?v00:(q==1)?v01:(q==2)?v10:v11;
                    if (cc < 512) g_u[(size_t)rr*512 + cc].x = vv;
                    else          g_u[(size_t)rr*512 + cc - 512].y = vv;
                }
            } else {
                float b0 = bias[c0], b1 = bias[c0 + 1];
                C[(size_t)r0*N + c0]         = v00 + b0;
                C[(size_t)r0*N + c0 + 1]     = v01 + b1;
                C[(size_t)(r0+8)*N + c0]     = v10 + b0;
                C[(size_t)(r0+8)*N + c0 + 1] = v11 + b1;
            }
        }
    }
}

extern "C" void kernel_launch(void* const* d_in, const int* in_sizes, int n_in,
                              void* d_out, int out_size)
{
    const float* x    = (const float*)d_in[0];
    const float* h0   = (const float*)d_in[1];
    const float* itoh = (const float*)d_in[2];
    const float* fcw  = (const float*)d_in[3];
    const float* fcb  = (const float*)d_in[4];
    const float* bh   = (const float*)d_in[5];
    const float* d1   = (const float*)d_in[6];
    const float* d2   = (const float*)d_in[7];
    const float* d3   = (const float*)d_in[8];
    const float* r1re = (const float*)d_in[9];
    const float* r1im = (const float*)d_in[10];
    const float* r2re = (const float*)d_in[11];
    const float* r2im = (const float*)d_in[12];
    const int*   perm = (const int*)d_in[13];
    float* out = (float*)d_out;

    cudaFuncSetAttribute(gemm_bf16s<0>, cudaFuncAttributeMaxDynamicSharedMemorySize, GEMM_SMEM);
    cudaFuncSetAttribute(gemm_bf16s<1>, cudaFuncAttributeMaxDynamicSharedMemorySize, GEMM_SMEM);

    {
        int n4 = (MROWS*IN_) / 4;
        split_kernel<0><<<(n4 + 255)/256, 256>>>(x, n4);
        n4 = (2*H_*IN_) / 4;
        split_kernel<1><<<(n4 + 255)/256, 256>>>(itoh, n4);
        n4 = (OUT_*2*H_) / 4;
        split_kernel<2><<<(n4 + 255)/256, 256>>>(fcw, n4);
    }

    gemm_bf16s<0><<<dim3(1024/64, MROWS/128), 256, GEMM_SMEM>>>(nullptr, nullptr,
                                                                MROWS, 1024, 256);
    scan_kernel<<<B_, 128>>>(h0, bh, d1, d2, d3, r1re, r1im, r2re, r2im, perm, out);
    gemm_bf16s<1><<<dim3(256/64, MROWS/128), 256, GEMM_SMEM>>>(fcb, out,
                                                               MROWS, 256, 1024);
}

// round 8
// speedup vs baseline: 1.8809x; 1.0789x over previous
#include <cuda_runtime.h>
#include <cuda_bf16.h>
#include <cstdint>

#define B_   64
#define T_   512
#define IN_  256
#define OUT_ 256
#define H_   512
#define MROWS (B_*T_)
#define OUT_OFF (B_*T_*OUT_)

__device__ __align__(16) float2 g_u[MROWS*H_];
__device__ __align__(16) __nv_bfloat16 g_outsH[MROWS*2*H_];
__device__ __align__(16) __nv_bfloat16 g_outsL[MROWS*2*H_];
__device__ __align__(16) __nv_bfloat16 g_xH[MROWS*IN_];
__device__ __align__(16) __nv_bfloat16 g_xL[MROWS*IN_];
__device__ __align__(16) __nv_bfloat16 g_w1H[2*H_*IN_];
__device__ __align__(16) __nv_bfloat16 g_w1L[2*H_*IN_];
__device__ __align__(16) __nv_bfloat16 g_w2H[OUT_*2*H_];
__device__ __align__(16) __nv_bfloat16 g_w2L[OUT_*2*H_];

__device__ __forceinline__ float2 cadd(float2 a, float2 b){return make_float2(a.x+b.x, a.y+b.y);}
__device__ __forceinline__ float2 csub(float2 a, float2 b){return make_float2(a.x-b.x, a.y-b.y);}
__device__ __forceinline__ float2 cmul(float2 a, float2 b){return make_float2(a.x*b.x-a.y*b.y, a.x*b.y+a.y*b.x);}
__device__ __forceinline__ float2 cmulc(float2 a, float2 b){return make_float2(a.x*b.x+a.y*b.y, a.y*b.x-a.x*b.y);}

// ---------------- packed f32x2 helpers (sm_103a) ----------------
__device__ __forceinline__ float2 p_add(float2 a, float2 b){
    float2 c;
    asm("{\n\t.reg .b64 ra,rb,rc;\n\t"
        "mov.b64 ra,{%2,%3};\n\tmov.b64 rb,{%4,%5};\n\t"
        "add.rn.f32x2 rc,ra,rb;\n\tmov.b64 {%0,%1},rc;\n\t}"
        : "=f"(c.x), "=f"(c.y)
        : "f"(a.x), "f"(a.y), "f"(b.x), "f"(b.y));
    return c;
}
__device__ __forceinline__ float2 p_fma(float2 a, float2 b, float2 c){  // a*b + c
    float2 d;
    asm("{\n\t.reg .b64 ra,rb,rc,rd;\n\t"
        "mov.b64 ra,{%2,%3};\n\tmov.b64 rb,{%4,%5};\n\tmov.b64 rc,{%6,%7};\n\t"
        "fma.rn.f32x2 rd,ra,rb,rc;\n\tmov.b64 {%0,%1},rd;\n\t}"
        : "=f"(d.x), "=f"(d.y)
        : "f"(a.x), "f"(a.y), "f"(b.x), "f"(b.y), "f"(c.x), "f"(c.y));
    return d;
}
#define P_SUB(a, b) p_fma((b), NEG1, (a))   // a - b  (NEG1 = (-1,-1) in scope)

template<int WHICH>
__global__ void split_kernel(const float* __restrict__ src, int n4)
{
    __nv_bfloat16 *hi, *lo;
    if (WHICH == 0) { hi = g_xH;  lo = g_xL;  }
    if (WHICH == 1) { hi = g_w1H; lo = g_w1L; }
    if (WHICH == 2) { hi = g_w2H; lo = g_w2L; }
    int i = blockIdx.x * blockDim.x + threadIdx.x;
    if (i >= n4) return;
    float4 v = ((const float4*)src)[i];
    const float* pv = (const float*)&v;
    #pragma unroll
    for (int j = 0; j < 4; j++) {
        __nv_bfloat16 h = __float2bfloat16(pv[j]);
        hi[4*i + j] = h;
        lo[4*i + j] = __float2bfloat16(pv[j] - __bfloat162float(h));
    }
}

// DFT-4 over 4 registers, packed. Forward W4=-i; inverse conj.
template<int INV>
__device__ __forceinline__ void dft4p(float2& x0, float2& x1, float2& x2, float2& x3,
                                      float2 NEG1)
{
    float2 t0 = p_add(x0, x2), t2 = P_SUB(x0, x2);
    float2 t1 = p_add(x1, x3), t3 = P_SUB(x1, x3);
    float2 w = INV ? make_float2(-t3.y, t3.x) : make_float2(t3.y, -t3.x);
    x0 = p_add(t0, t1);
    x2 = P_SUB(t0, t1);
    x1 = p_add(t2, w);
    x3 = P_SUB(t2, w);
}

// DIF radix-2 FFT-32 across lanes on 4 regs; output at lane l = comp rev5(l).
template<int INV>
__device__ __forceinline__ void fft32(float2 y[4], const float2 tw32[5], int lane,
                                      float2 NEG1)
{
    #pragma unroll
    for (int s = 0; s < 5; s++) {
        const int st = 16 >> s;
        const bool hi = (lane & st) != 0;
        const float2 tw = tw32[s];
        #pragma unroll
        for (int j = 0; j < 4; j++) {
            float2 v = y[j], pv;
            pv.x = __shfl_xor_sync(0xffffffffu, v.x, st);
            pv.y = __shfl_xor_sync(0xffffffffu, v.y, st);
            float2 sum = p_add(v, pv);
            float2 dif = P_SUB(pv, v);
            float2 tv  = INV ? cmulc(dif, tw) : cmul(dif, tw);
            y[j] = hi ? tv : sum;
        }
    }
}

// =========================================================================
// Scan: 1 chain/CTA, 128 thr, hybrid FFT, linearity-hoisted reflections,
// 4 syncs/step, packed f32x2 butterflies, MUFU modReLU.
// =========================================================================
__global__ __launch_bounds__(128)
void scan_kernel(const float* __restrict__ h0,
                 const float* __restrict__ b_h,
                 const float* __restrict__ d1,
                 const float* __restrict__ d2,
                 const float* __restrict__ d3,
                 const float* __restrict__ r1re, const float* __restrict__ r1im,
                 const float* __restrict__ r2re, const float* __restrict__ r2im,
                 const int*   __restrict__ perm,
                 float* __restrict__ dout)
{
    __shared__ float2 SA[544], SB[544];
    __shared__ float2 WE3[544], WE3s[544], V2E3[544], V2E3s[544];
    __shared__ float2 RED1[4], RED2[4];
    __shared__ float  FAC[2];

    const int b    = blockIdx.x;
    const int tid  = threadIdx.x;
    const int lane = tid & 31;
    const int w    = tid >> 5;
    const int R    = __brev(lane) >> 27;      // rev5(lane)
    const float2 NEG1 = make_float2(-1.f, -1.f);

    int oaddr[4];
    #pragma unroll
    for (int j = 0; j < 4; j++) oaddr[j] = R*17 + w + 4*j;

    float2 h[4], e1r[4], e2r[4], e3r[4], v1o[4], v2o[4];
    float bhr[4]; int paddr[4], caddr[4];
    const float inv512 = 1.0f / 512.0f;
    #pragma unroll
    for (int r = 0; r < 4; r++) {
        int idx = tid + 128*r;
        float sn, cs;
        sincosf(d1[idx], &sn, &cs); e1r[r] = make_float2(cs, sn);
        sincosf(d2[idx], &sn, &cs); e2r[r] = make_float2(cs, sn);
        sincosf(d3[idx], &sn, &cs); e3r[r] = make_float2(cs*inv512, sn*inv512);
        bhr[r] = b_h[idx];
        int p = perm[idx];
        paddr[r] = (p >> 4)*17 + (p & 15);
        caddr[r] = (idx >> 4)*17 + (idx & 15);
        h[r] = make_float2(h0[b*1024 + idx], h0[b*1024 + 512 + idx]);
    }
    #pragma unroll
    for (int j = 0; j < 4; j++) {
        int oi = w + 4*j + 16*R;
        v1o[j] = make_float2(r1re[oi], r1im[oi]);
        v2o[j] = make_float2(r2re[oi], r2im[oi]);
    }

    const float TWO_PI = 6.283185307179586f;
    float2 c512[3], d128[3], tw32c[5];
    #pragma unroll
    for (int k = 1; k <= 3; k++) {
        float sn, cs;
        sincosf(-TWO_PI * (float)(tid*k) / 512.0f, &sn, &cs);
        c512[k-1] = make_float2(cs, sn);
        sincosf(-TWO_PI * (float)(lane*k) / 128.0f, &sn, &cs);
        d128[k-1] = make_float2(cs, sn);
    }
    #pragma unroll
    for (int s = 0; s < 5; s++) {
        int st = 16 >> s;
        int e  = (lane & (st - 1)) << s;
        float sn, cs;
        sincosf(-TWO_PI * (float)e / 32.0f, &sn, &cs);
        tw32c[s] = make_float2(cs, sn);
    }

    // ---- fac1/fac2 ----
    {
        float n1 = 0.f, n2 = 0.f;
        #pragma unroll
        for (int r = 0; r < 4; r++) {
            int idx = tid + 128*r;
            n1 += r1re[idx]*r1re[idx] + r1im[idx]*r1im[idx];
            n2 += r2re[idx]*r2re[idx] + r2im[idx]*r2im[idx];
        }
        #pragma unroll
        for (int off = 16; off; off >>= 1) {
            n1 += __shfl_xor_sync(0xffffffffu, n1, off);
            n2 += __shfl_xor_sync(0xffffffffu, n2, off);
        }
        if (lane == 0) RED1[w] = make_float2(n1, n2);
        __syncthreads();
        if (tid == 0) {
            float a  = (RED1[0].x + RED1[1].x) + (RED1[2].x + RED1[3].x);
            float bb = (RED1[0].y + RED1[1].y) + (RED1[2].y + RED1[3].y);
            FAC[0] = 2.f / a; FAC[1] = 2.f / bb;
        }
        __syncthreads();
    }
    const float fac1 = FAC[0], fac2 = FAC[1];

    // ---- precompute W = IFFT(P(v1).e2), K = fac2<W,v2>, tables ----
    float Kx, Ky;
    {
        for (int i = tid; i < 512; i += 128) {
            int a = (i >> 4)*17 + (i & 15);
            SB[a] = make_float2(r1re[i], r1im[i]);
        }
        __syncthreads();
        float2 yw[4];
        #pragma unroll
        for (int r = 0; r < 4; r++) yw[r] = cmul(SB[paddr[r]], e2r[r]);
        dft4p<1>(yw[0], yw[1], yw[2], yw[3], NEG1);
        yw[1] = cmulc(yw[1], c512[0]);
        yw[2] = cmulc(yw[2], c512[1]);
        yw[3] = cmulc(yw[3], c512[2]);
        #pragma unroll
        for (int r = 0; r < 4; r++) SA[r*128 + tid] = yw[r];
        __syncthreads();
        #pragma unroll
        for (int q = 0; q < 4; q++) yw[q] = SA[w*128 + 32*q + lane];
        dft4p<1>(yw[0], yw[1], yw[2], yw[3], NEG1);
        yw[1] = cmulc(yw[1], d128[0]);
        yw[2] = cmulc(yw[2], d128[1]);
        yw[3] = cmulc(yw[3], d128[2]);
        fft32<1>(yw, tw32c, lane, NEG1);

        float dx = 0.f, dy = 0.f;
        #pragma unroll
        for (int j = 0; j < 4; j++) {
            dx += yw[j].x*v2o[j].x + yw[j].y*v2o[j].y;
            dy += yw[j].y*v2o[j].x - yw[j].x*v2o[j].y;
        }
        #pragma unroll
        for (int off = 16; off; off >>= 1) {
            dx += __shfl_xor_sync(0xffffffffu, dx, off);
            dy += __shfl_xor_sync(0xffffffffu, dy, off);
        }
        if (lane == 0) RED2[w] = make_float2(dx, dy);
        #pragma unroll
        for (int j = 0; j < 4; j++) SB[oaddr[j]] = yw[j];
        __syncthreads();
        Kx = ((RED2[0].x + RED2[1].x) + (RED2[2].x + RED2[3].x)) * fac2;
        Ky = ((RED2[0].y + RED2[1].y) + (RED2[2].y + RED2[3].y)) * fac2;
        for (int i = tid; i < 512; i += 128) {
            int a = (i >> 4)*17 + (i & 15);
            float sn, cs; sincosf(d3[i], &sn, &cs);
            float2 e3i = make_float2(cs*inv512, sn*inv512);
            float2 we  = cmul(SB[a], e3i);
            float2 ve  = cmul(make_float2(r2re[i], r2im[i]), e3i);
            WE3[a]   = we;
            WE3s[a]  = make_float2(we.y, -we.x);
            V2E3[a]  = ve;
            V2E3s[a] = make_float2(ve.y, -ve.x);
        }
        __syncthreads();
    }

    const int brow = b * T_;

    for (int t = 0; t < T_; t++) {
        float2 u0[4];
        {
            const float2* up = g_u + (size_t)(brow + t) * H_;
            #pragma unroll
            for (int r = 0; r < 4; r++) u0[r] = up[tid + 128*r];
        }

        // ph1: fwd FFT part 1
        float2 y[4];
        #pragma unroll
        for (int r = 0; r < 4; r++) y[r] = cmul(h[r], e1r[r]);
        dft4p<0>(y[0], y[1], y[2], y[3], NEG1);
        y[1] = cmul(y[1], c512[0]);
        y[2] = cmul(y[2], c512[1]);
        y[3] = cmul(y[3], c512[2]);
        #pragma unroll
        for (int r = 0; r < 4; r++) SA[r*128 + tid] = y[r];
        __syncthreads();                                              // S1

        // ph2: fwd FFT part 2 -> z owned; publish z + dot1 partials
        #pragma unroll
        for (int q = 0; q < 4; q++) y[q] = SA[w*128 + 32*q + lane];
        dft4p<0>(y[0], y[1], y[2], y[3], NEG1);
        y[1] = cmul(y[1], d128[0]);
        y[2] = cmul(y[2], d128[1]);
        y[3] = cmul(y[3], d128[2]);
        fft32<0>(y, tw32c, lane, NEG1);
        #pragma unroll
        for (int j = 0; j < 4; j++) SB[oaddr[j]] = y[j];
        {
            float dx = 0.f, dy = 0.f;
            #pragma unroll
            for (int j = 0; j < 4; j++) {
                dx += y[j].x*v1o[j].x + y[j].y*v1o[j].y;
                dy += y[j].y*v1o[j].x - y[j].x*v1o[j].y;
            }
            #pragma unroll
            for (int off = 16; off; off >>= 1) {
                dx += __shfl_xor_sync(0xffffffffu, dx, off);
                dy += __shfl_xor_sync(0xffffffffu, dy, off);
            }
            if (lane == 0) RED1[w] = make_float2(dx, dy);
        }
        __syncthreads();                                              // S2

        // ph3: gather permuted z * e2; IFFT part 1
        #pragma unroll
        for (int r = 0; r < 4; r++) y[r] = cmul(SB[paddr[r]], e2r[r]);
        dft4p<1>(y[0], y[1], y[2], y[3], NEG1);
        y[1] = cmulc(y[1], c512[0]);
        y[2] = cmulc(y[2], c512[1]);
        y[3] = cmulc(y[3], c512[2]);
        #pragma unroll
        for (int r = 0; r < 4; r++) SA[r*128 + tid] = y[r];
        __syncthreads();                                              // S3

        // ph4: IFFT part 2 -> y0 owned; dot2 partials; publish y0
        #pragma unroll
        for (int q = 0; q < 4; q++) y[q] = SA[w*128 + 32*q + lane];
        dft4p<1>(y[0], y[1], y[2], y[3], NEG1);
        y[1] = cmulc(y[1], d128[0]);
        y[2] = cmulc(y[2], d128[1]);
        y[3] = cmulc(y[3], d128[2]);
        fft32<1>(y, tw32c, lane, NEG1);
        #pragma unroll
        for (int j = 0; j < 4; j++) SB[oaddr[j]] = y[j];
        {
            float dx = 0.f, dy = 0.f;
            #pragma unroll
            for (int j = 0; j < 4; j++) {
                dx += y[j].x*v2o[j].x + y[j].y*v2o[j].y;
                dy += y[j].y*v2o[j].x - y[j].x*v2o[j].y;
            }
            #pragma unroll
            for (int off = 16; off; off >>= 1) {
                dx += __shfl_xor_sync(0xffffffffu, dx, off);
                dy += __shfl_xor_sync(0xffffffffu, dy, off);
            }
            if (lane == 0) RED2[w] = make_float2(dx, dy);
        }
        __syncthreads();                                              // S4

        // ph5: epilogue
        float2 c1, c2;
        c1.x = ((RED1[0].x + RED1[1].x) + (RED1[2].x + RED1[3].x)) * fac1;
        c1.y = ((RED1[0].y + RED1[1].y) + (RED1[2].y + RED1[3].y)) * fac1;
        float d2x = (RED2[0].x + RED2[1].x) + (RED2[2].x + RED2[3].x);
        float d2y = (RED2[0].y + RED2[1].y) + (RED2[2].y + RED2[3].y);
        c2.x = fac2*d2x - (c1.x*Kx - c1.y*Ky);
        c2.y = fac2*d2y - (c1.x*Ky + c1.y*Kx);

        // splats for packed corrections:
        //   s -= c ⊛ v  <=>  s = fma2((c.y,c.y), (v.y,-v.x), s); s = fma2((-c.x,-c.x), v, s)
        const float2 c1nx = make_float2(-c1.x, -c1.x), c1y = make_float2(c1.y, c1.y);
        const float2 c2nx = make_float2(-c2.x, -c2.x), c2y = make_float2(c2.y, c2.y);

        const int orow = (brow + t) * (2*H_);
        #pragma unroll
        for (int r = 0; r < 4; r++) {
            int a = caddr[r];
            float2 y0c = SB[a];
            float2 s = cmul(y0c, e3r[r]);
            s = p_fma(c1y,  WE3s[a], s);
            s = p_fma(c1nx, WE3[a],  s);
            s = p_fma(c2y,  V2E3s[a], s);
            s = p_fma(c2nx, V2E3[a],  s);
            float2 pre = p_add(u0[r], s);
            float n2v = pre.x*pre.x + pre.y*pre.y;
            float rn  = rsqrtf(fmaxf(n2v, 1e-18f));
            float norm = n2v * rn;
            float sc = fmaxf(norm + bhr[r], 0.f) * __fdividef(1.f, norm + 1e-6f);
            float2 nw = make_float2(pre.x*sc, pre.y*sc);
            h[r] = nw;
            int idx = tid + 128*r;
            __nv_bfloat16 hx = __float2bfloat16(nw.x);
            __nv_bfloat16 hy = __float2bfloat16(nw.y);
            g_outsH[orow + idx]       = hx;
            g_outsL[orow + idx]       = __float2bfloat16(nw.x - __bfloat162float(hx));
            g_outsH[orow + 512 + idx] = hy;
            g_outsL[orow + 512 + idx] = __float2bfloat16(nw.y - __bfloat162float(hy));
        }
    }

    #pragma unroll
    for (int r = 0; r < 4; r++) {
        int idx = tid + 128*r;
        dout[OUT_OFF + b*1024 + idx]       = h[r].x;
        dout[OUT_OFF + b*1024 + 512 + idx] = h[r].y;
    }
}

// =========================================================================
// bf16x3 GEMM: pre-split operands, cp.async double buffer, ldmatrix frags
// =========================================================================
#define MMA16816(d, a, b)                                                     \
    asm volatile("mma.sync.aligned.m16n8k16.row.col.f32.bf16.bf16.f32 "       \
                 "{%0,%1,%2,%3}, {%4,%5,%6,%7}, {%8,%9}, {%0,%1,%2,%3};\n"    \
                 : "+f"(d[0]), "+f"(d[1]), "+f"(d[2]), "+f"(d[3])             \
                 : "r"(a[0]), "r"(a[1]), "r"(a[2]), "r"(a[3]),                \
                   "r"(b[0]), "r"(b[1]))

#define LDMX4(r0, r1, r2, r3, addr)                                           \
    asm volatile("ldmatrix.sync.aligned.m8n8.x4.shared.b16 {%0,%1,%2,%3}, [%4];" \
                 : "=r"(r0), "=r"(r1), "=r"(r2), "=r"(r3) : "r"(addr))

__device__ __forceinline__ void cp16(void* dst, const void* src) {
    uint32_t d = (uint32_t)__cvta_generic_to_shared(dst);
    asm volatile("cp.async.cg.shared.global [%0], [%1], 16;\n" :: "r"(d), "l"(src));
}

#define AS(p, buf, hl, r, c) (p)[((((buf)*2 + (hl))*128 + (r))*40) + (c)]
#define BS(p, buf, hl, r, c) (p)[((((buf)*2 + (hl))*64  + (r))*40) + (c)]
#define GEMM_SMEM ((2*2*128*40 + 2*2*64*40) * 2)

template<int MODE>
__global__ __launch_bounds__(256)
void gemm_bf16s(const float* __restrict__ bias,
                float* __restrict__ C, int M, int N, int K)
{
    extern __shared__ __nv_bfloat16 smem[];
    __nv_bfloat16* Asm = smem;
    __nv_bfloat16* Bsm = smem + 2*2*128*40;

    const __nv_bfloat16* AH = (MODE == 0) ? g_xH : g_outsH;
    const __nv_bfloat16* AL = (MODE == 0) ? g_xL : g_outsL;
    const __nv_bfloat16* WH = (MODE == 0) ? g_w1H : g_w2H;
    const __nv_bfloat16* WL = (MODE == 0) ? g_w1L : g_w2L;

    const int tid = threadIdx.x;
    const int wid = tid >> 5, lane = tid & 31;
    const int wm = wid >> 1, wn = wid & 1;
    const int groupID = lane >> 2, tig = lane & 3;
    const int bm0 = blockIdx.y * 128;
    const int bn0 = blockIdx.x * 64;
    const int KT = K / 32;

    const int ar0 = tid >> 2,         aq0 = (tid & 3) * 8;
    const int ar1 = (tid + 256) >> 2, aq1 = aq0;
    const int br  = tid >> 2,         bq  = (tid & 3) * 8;

    const int a_row = (lane & 15);
    const int a_col = (lane >> 4) * 8;
    const int b_row = ((lane >> 4) << 3) + (lane & 7);
    const int b_col = ((lane >> 3) & 1) * 8;

    float acc[2][4][4];
    #pragma unroll
    for (int mi = 0; mi < 2; mi++)
        #pragma unroll
        for (int ni = 0; ni < 4; ni++)
            #pragma unroll
            for (int j = 0; j < 4; j++) acc[mi][ni][j] = 0.f;

    auto load_tile = [&](int kt, int buf) {
        int k0 = kt * 32;
        cp16(&AS(Asm, buf, 0, ar0, aq0), AH + (size_t)(bm0 + ar0)*K + k0 + aq0);
        cp16(&AS(Asm, buf, 0, ar1, aq1), AH + (size_t)(bm0 + ar1)*K + k0 + aq1);
        cp16(&AS(Asm, buf, 1, ar0, aq0), AL + (size_t)(bm0 + ar0)*K + k0 + aq0);
        cp16(&AS(Asm, buf, 1, ar1, aq1), AL + (size_t)(bm0 + ar1)*K + k0 + aq1);
        cp16(&BS(Bsm, buf, 0, br, bq),   WH + (size_t)(bn0 + br)*K + k0 + bq);
        cp16(&BS(Bsm, buf, 1, br, bq),   WL + (size_t)(bn0 + br)*K + k0 + bq);
    };

    load_tile(0, 0);
    asm volatile("cp.async.commit_group;\n");

    for (int kt = 0; kt < KT; kt++) {
        const int buf = kt & 1;
        if (kt + 1 < KT) {
            load_tile(kt + 1, (kt + 1) & 1);
            asm volatile("cp.async.commit_group;\n");
            asm volatile("cp.async.wait_group 1;\n");
        } else {
            asm volatile("cp.async.wait_group 0;\n");
        }
        __syncthreads();

        #pragma unroll
        for (int kk = 0; kk < 2; kk++) {
            const int kb = kk * 16;
            uint32_t aH[2][4], aL[2][4], bH[4][2], bL[4][2];
            #pragma unroll
            for (int mi = 0; mi < 2; mi++) {
                uint32_t adrH = (uint32_t)__cvta_generic_to_shared(
                    &AS(Asm, buf, 0, wm*32 + mi*16 + a_row, kb + a_col));
                uint32_t adrL = (uint32_t)__cvta_generic_to_shared(
                    &AS(Asm, buf, 1, wm*32 + mi*16 + a_row, kb + a_col));
                LDMX4(aH[mi][0], aH[mi][1], aH[mi][2], aH[mi][3], adrH);
                LDMX4(aL[mi][0], aL[mi][1], aL[mi][2], aL[mi][3], adrL);
            }
            #pragma unroll
            for (int nip = 0; nip < 2; nip++) {
                uint32_t adrH = (uint32_t)__cvta_generic_to_shared(
                    &BS(Bsm, buf, 0, wn*32 + nip*16 + b_row, kb + b_col));
                uint32_t adrL = (uint32_t)__cvta_generic_to_shared(
                    &BS(Bsm, buf, 1, wn*32 + nip*16 + b_row, kb + b_col));
                LDMX4(bH[2*nip][0], bH[2*nip][1], bH[2*nip+1][0], bH[2*nip+1][1], adrH);
                LDMX4(bL[2*nip][0], bL[2*nip][1], bL[2*nip+1][0], bL[2*nip+1][1], adrL);
            }
            #pragma unroll
            for (int mi = 0; mi < 2; mi++)
                #pragma unroll
                for (int ni = 0; ni < 4; ni++) {
                    MMA16816(acc[mi][ni], aH[mi], bH[ni]);
                    MMA16816(acc[mi][ni], aH[mi], bL[ni]);
                    MMA16816(acc[mi][ni], aL[mi], bH[ni]);
                }
        }
        __syncthreads();
    }

    #pragma unroll
    for (int mi = 0; mi < 2; mi++) {
        #pragma unroll
        for (int ni = 0; ni < 4; ni++) {
            int r0 = bm0 + wm*32 + mi*16 + groupID;
            int c0 = bn0 + wn*32 + ni*8 + 2*tig;
            float v00 = acc[mi][ni][0], v01 = acc[mi][ni][1];
            float v10 = acc[mi][ni][2], v11 = acc[mi][ni][3];
            if (MODE == 0) {
                #pragma unroll
                for (int q = 0; q < 4; q++) {
                    int rr = (q < 2) ? r0 : (r0 + 8);
                    int cc = (q & 1) ? (c0 + 1) : c0;
                    float vv = (q==0)?v00:(q==1)?v01:(q==2)?v10:v11;
                    if (cc < 512) g_u[(size_t)rr*512 + cc].x = vv;
                    else          g_u[(size_t)rr*512 + cc - 512].y = vv;
                }
            } else {
                float b0 = bias[c0], b1 = bias[c0 + 1];
                C[(size_t)r0*N + c0]         = v00 + b0;
                C[(size_t)r0*N + c0 + 1]     = v01 + b1;
                C[(size_t)(r0+8)*N + c0]     = v10 + b0;
                C[(size_t)(r0+8)*N + c0 + 1] = v11 + b1;
            }
        }
    }
}

extern "C" void kernel_launch(void* const* d_in, const int* in_sizes, int n_in,
                              void* d_out, int out_size)
{
    const float* x    = (const float*)d_in[0];
    const float* h0   = (const float*)d_in[1];
    const float* itoh = (const float*)d_in[2];
    const float* fcw  = (const float*)d_in[3];
    const float* fcb  = (const float*)d_in[4];
    const float* bh   = (const float*)d_in[5];
    const float* d1   = (const float*)d_in[6];
    const float* d2   = (const float*)d_in[7];
    const float* d3   = (const float*)d_in[8];
    const float* r1re = (const float*)d_in[9];
    const float* r1im = (const float*)d_in[10];
    const float* r2re = (const float*)d_in[11];
    const float* r2im = (const float*)d_in[12];
    const int*   perm = (const int*)d_in[13];
    float* out = (float*)d_out;

    cudaFuncSetAttribute(gemm_bf16s<0>, cudaFuncAttributeMaxDynamicSharedMemorySize, GEMM_SMEM);
    cudaFuncSetAttribute(gemm_bf16s<1>, cudaFuncAttributeMaxDynamicSharedMemorySize, GEMM_SMEM);

    {
        int n4 = (MROWS*IN_) / 4;
        split_kernel<0><<<(n4 + 255)/256, 256>>>(x, n4);
        n4 = (2*H_*IN_) / 4;
        split_kernel<1><<<(n4 + 255)/256, 256>>>(itoh, n4);
        n4 = (OUT_*2*H_) / 4;
        split_kernel<2><<<(n4 + 255)/256, 256>>>(fcw, n4);
    }

    gemm_bf16s<0><<<dim3(1024/64, MROWS/128), 256, GEMM_SMEM>>>(nullptr, nullptr,
                                                                MROWS, 1024, 256);
    scan_kernel<<<B_, 128>>>(h0, bh, d1, d2, d3, r1re, r1im, r2re, r2im, perm, out);
    gemm_bf16s<1><<<dim3(256/64, MROWS/128), 256, GEMM_SMEM>>>(fcb, out,
                                                               MROWS, 256, 1024);
}